// round 2
// baseline (speedup 1.0000x reference)
#include <cuda_runtime.h>

#define B_ 64
#define N_ 4096
#define D_ 256
#define S_ 8
#define H_ 512
#define CHUNKS 16

// ---------------- scratch (device globals; no allocation allowed) ----------------
__device__ float g_k[B_*N_*D_];            // 256 MB
__device__ float g_v[B_*N_*D_];            // 256 MB
__device__ float g_slots[B_*S_*D_];
__device__ float g_q[B_*S_*D_];
__device__ float g_upd[B_*S_*D_];
__device__ float g_updp[B_*CHUNKS*S_*D_];  // 13 MB partials
__device__ float g_colp[B_*CHUNKS*S_];

// ---------------- f32x2 packed-FMA helpers (sm_10x, PTX-only path) ---------------
__device__ __forceinline__ unsigned long long pack2(float lo, float hi) {
    unsigned long long r;
    asm("mov.b64 %0, {%1, %2};" : "=l"(r) : "f"(lo), "f"(hi));
    return r;
}
__device__ __forceinline__ unsigned long long ffma2(unsigned long long a,
                                                    unsigned long long b,
                                                    unsigned long long c) {
    unsigned long long d;
    asm("fma.rn.f32x2 %0, %1, %2, %3;" : "=l"(d) : "l"(a), "l"(b), "l"(c));
    return d;
}
__device__ __forceinline__ float2 unpack2(unsigned long long v) {
    float lo, hi;
    asm("mov.b64 {%0, %1}, %2;" : "=f"(lo), "=f"(hi) : "l"(v));
    return make_float2(lo, hi);
}

// =================================================================================
// K0: slots = mu + exp(log_sigma) * noise    (B*S*D = 131072 elems)
// =================================================================================
__global__ void k0_init(const float* __restrict__ noise,
                        const float* __restrict__ mu,
                        const float* __restrict__ ls) {
    int i = blockIdx.x * 256 + threadIdx.x;
    int d = i & 255;
    g_slots[i] = mu[d] + expf(ls[d]) * noise[i];
}

// =================================================================================
// K1: fused LayerNorm + k/v projection.
// grid (4096, 2): x = 64-token tile, y selects (Wk->g_k) / (Wv->g_v). 256 threads.
// dyn smem: xs[64][257] | ws[32][256] | lw[256] | lb[256]  = 100608 B
// =================================================================================
__global__ void __launch_bounds__(256) k1_proj(
    const float* __restrict__ inp, const float* __restrict__ Wk,
    const float* __restrict__ Wv, const float* __restrict__ lnw,
    const float* __restrict__ lnb)
{
    extern __shared__ float sm[];
    float* xs = sm;                  // [64][257]
    float* ws = sm + 64 * 257;       // [32][256]
    float* lw = ws + 32 * 256;
    float* lb = lw + 256;

    int tid = threadIdx.x;
    const float* W = (blockIdx.y == 0) ? Wk : Wv;
    float* outp = (blockIdx.y == 0) ? g_k : g_v;
    long tok0 = (long)blockIdx.x * 64;

    lw[tid] = lnw[tid];
    lb[tid] = lnb[tid];

    // ---- LN phase: 4 threads per token, each owns 64 contiguous dims ----
    int tok = tid >> 2, r = tid & 3;
    float xv[64];
    const float4* xr = (const float4*)(inp + (tok0 + tok) * 256 + r * 64);
#pragma unroll
    for (int j = 0; j < 16; j++) {
        float4 t = xr[j];
        xv[4*j+0] = t.x; xv[4*j+1] = t.y; xv[4*j+2] = t.z; xv[4*j+3] = t.w;
    }
    float s1 = 0.f, s2 = 0.f;
#pragma unroll
    for (int j = 0; j < 64; j++) { s1 += xv[j]; s2 += xv[j] * xv[j]; }
    s1 += __shfl_xor_sync(0xffffffffu, s1, 1);
    s2 += __shfl_xor_sync(0xffffffffu, s2, 1);
    s1 += __shfl_xor_sync(0xffffffffu, s1, 2);
    s2 += __shfl_xor_sync(0xffffffffu, s2, 2);
    float mean = s1 * (1.0f / 256.0f);
    float var  = s2 * (1.0f / 256.0f) - mean * mean;
    float rs   = rsqrtf(var + 1e-5f);
    __syncthreads();                       // lw/lb ready
#pragma unroll
    for (int j = 0; j < 64; j++) {
        int d = r * 64 + j;
        xs[tok * 257 + d] = (xv[j] - mean) * rs * lw[d] + lb[d];
    }

    // ---- GEMM phase: thread tile = 8 tokens x 8 outdims, f32x2 accumulate ----
    int tx = tid & 31, ty = tid >> 5;
    int t0 = ty * 8, n0 = tx * 8;
    unsigned long long acc[8][4];
#pragma unroll
    for (int i = 0; i < 8; i++)
#pragma unroll
        for (int j = 0; j < 4; j++) acc[i][j] = pack2(0.f, 0.f);

    for (int kc = 0; kc < 256; kc += 32) {
        __syncthreads();                   // also orders xs writes before reads
        {   // stage W[n][kc..kc+31] transposed -> ws[kk][n]
            const float4* wr = (const float4*)(W + tid * 256 + kc);
#pragma unroll
            for (int j = 0; j < 8; j++) {
                float4 w4 = wr[j];
                ws[(4*j+0) * 256 + tid] = w4.x;
                ws[(4*j+1) * 256 + tid] = w4.y;
                ws[(4*j+2) * 256 + tid] = w4.z;
                ws[(4*j+3) * 256 + tid] = w4.w;
            }
        }
        __syncthreads();
#pragma unroll 4
        for (int kk = 0; kk < 32; kk++) {
            unsigned long long xd[8];
#pragma unroll
            for (int i = 0; i < 8; i++) {
                float xvv = xs[(t0 + i) * 257 + kc + kk];  // warp broadcast
                xd[i] = pack2(xvv, xvv);
            }
            ulonglong2 wa = *(const ulonglong2*)(ws + kk * 256 + n0);
            ulonglong2 wb = *(const ulonglong2*)(ws + kk * 256 + n0 + 4);
#pragma unroll
            for (int i = 0; i < 8; i++) {
                acc[i][0] = ffma2(xd[i], wa.x, acc[i][0]);
                acc[i][1] = ffma2(xd[i], wa.y, acc[i][1]);
                acc[i][2] = ffma2(xd[i], wb.x, acc[i][2]);
                acc[i][3] = ffma2(xd[i], wb.y, acc[i][3]);
            }
        }
    }
#pragma unroll
    for (int i = 0; i < 8; i++) {
        float2 a0 = unpack2(acc[i][0]);
        float2 a1 = unpack2(acc[i][1]);
        float2 a2 = unpack2(acc[i][2]);
        float2 a3 = unpack2(acc[i][3]);
        float4* o = (float4*)(outp + (tok0 + t0 + i) * 256 + n0);
        o[0] = make_float4(a0.x, a0.y, a1.x, a1.y);
        o[1] = make_float4(a2.x, a2.y, a3.x, a3.y);
    }
}

// =================================================================================
// K3: q = LN(slots) @ Wq^T * scale.  grid 64 (batch), 256 threads.
// =================================================================================
__global__ void __launch_bounds__(256) k3_q(
    const float* __restrict__ Wq, const float* __restrict__ lnw,
    const float* __restrict__ lnb)
{
    __shared__ float sn[8 * 256];
    int tid = threadIdx.x, b = blockIdx.x;
    int r = tid >> 5, l = tid & 31;

    const float4* sr = (const float4*)(g_slots + (b * 8 + r) * 256);
    float4 v0 = sr[l * 2], v1 = sr[l * 2 + 1];
    float s1 = v0.x + v0.y + v0.z + v0.w + v1.x + v1.y + v1.z + v1.w;
    float s2 = v0.x*v0.x + v0.y*v0.y + v0.z*v0.z + v0.w*v0.w
             + v1.x*v1.x + v1.y*v1.y + v1.z*v1.z + v1.w*v1.w;
#pragma unroll
    for (int off = 16; off >= 1; off >>= 1) {
        s1 += __shfl_xor_sync(0xffffffffu, s1, off);
        s2 += __shfl_xor_sync(0xffffffffu, s2, off);
    }
    float mean = s1 * (1.0f / 256.0f);
    float var  = s2 * (1.0f / 256.0f) - mean * mean;
    float rs   = rsqrtf(var + 1e-5f);
    int d0 = l * 8;
    sn[r*256 + d0 + 0] = (v0.x - mean) * rs * lnw[d0+0] + lnb[d0+0];
    sn[r*256 + d0 + 1] = (v0.y - mean) * rs * lnw[d0+1] + lnb[d0+1];
    sn[r*256 + d0 + 2] = (v0.z - mean) * rs * lnw[d0+2] + lnb[d0+2];
    sn[r*256 + d0 + 3] = (v0.w - mean) * rs * lnw[d0+3] + lnb[d0+3];
    sn[r*256 + d0 + 4] = (v1.x - mean) * rs * lnw[d0+4] + lnb[d0+4];
    sn[r*256 + d0 + 5] = (v1.y - mean) * rs * lnw[d0+5] + lnb[d0+5];
    sn[r*256 + d0 + 6] = (v1.z - mean) * rs * lnw[d0+6] + lnb[d0+6];
    sn[r*256 + d0 + 7] = (v1.w - mean) * rs * lnw[d0+7] + lnb[d0+7];
    __syncthreads();

    float acc[8] = {0,0,0,0,0,0,0,0};
    const float4* wr  = (const float4*)(Wq + tid * 256);
    const float4* sn4 = (const float4*)sn;
    for (int d4 = 0; d4 < 64; d4++) {
        float4 w = wr[d4];
#pragma unroll
        for (int rr = 0; rr < 8; rr++) {
            float4 s = sn4[rr * 64 + d4];
            acc[rr] += w.x*s.x + w.y*s.y + w.z*s.z + w.w*s.w;
        }
    }
    const float scale = 0.0625f;  // 256^-0.5
#pragma unroll
    for (int rr = 0; rr < 8; rr++)
        g_q[(b * 8 + rr) * 256 + tid] = acc[rr] * scale;
}

// =================================================================================
// K4: fused logits + softmax(+eps) + unnormalized updates, per 256-token chunk.
// grid (16, 64) = (chunk, batch), 256 threads.
// =================================================================================
__global__ void __launch_bounds__(256) k4_attn()
{
    __shared__ float qs[8 * 256];
    __shared__ float attnw[256][8];
    __shared__ float wcs[8][8];    // per-warp colsum partials [warp][slot]
    int tid = threadIdx.x;
    int b = blockIdx.y, chunk = blockIdx.x;
    long tok0 = (long)b * 4096 + (long)chunk * 256;

    for (int i = tid; i < 2048; i += 256) qs[i] = g_q[b * 2048 + i];
    __syncthreads();

    int w = tid >> 5, l = tid & 31;
    float csum[8];
#pragma unroll
    for (int s = 0; s < 8; s++) csum[s] = 0.f;
    const float4* qs4 = (const float4*)qs;

    for (int it = 0; it < 32; it++) {
        int tl = w + it * 8;                       // local token, warp-strided
        const float4* kr = (const float4*)(g_k + (tok0 + tl) * 256);
        float4 k0 = kr[l * 2], k1 = kr[l * 2 + 1];
        float p[8];
#pragma unroll
        for (int s = 0; s < 8; s++) {
            float4 q0 = qs4[s * 64 + l * 2];
            float4 q1 = qs4[s * 64 + l * 2 + 1];
            p[s] = k0.x*q0.x + k0.y*q0.y + k0.z*q0.z + k0.w*q0.w
                 + k1.x*q1.x + k1.y*q1.y + k1.z*q1.z + k1.w*q1.w;
        }
#pragma unroll
        for (int off = 16; off >= 1; off >>= 1)
#pragma unroll
            for (int s = 0; s < 8; s++)
                p[s] += __shfl_xor_sync(0xffffffffu, p[s], off);
        float mx = p[0];
#pragma unroll
        for (int s = 1; s < 8; s++) mx = fmaxf(mx, p[s]);
        float e[8], se = 0.f;
#pragma unroll
        for (int s = 0; s < 8; s++) { e[s] = expf(p[s] - mx); se += e[s]; }
        float inv = 1.0f / se;
#pragma unroll
        for (int s = 0; s < 8; s++) { e[s] = e[s] * inv + 1e-8f; csum[s] += e[s]; }
        if (l < 8) attnw[tl][l] = e[l];
    }
    if (l < 8) wcs[w][l] = csum[l];      // deterministic reduction (no atomics)
    __syncthreads();
    if (tid < 8) {
        float c = 0.f;
#pragma unroll
        for (int wi = 0; wi < 8; wi++) c += wcs[wi][tid];
        g_colp[(b * 16 + chunk) * 8 + tid] = c;
    }

    // phase 2: updates partial.  warp = slot, lane = 8-dim group.
    int s = tid >> 5, g = tid & 31;
    float4 A0 = make_float4(0,0,0,0), A1 = make_float4(0,0,0,0);
    const float4* vb = (const float4*)(g_v + tok0 * 256);
#pragma unroll 4
    for (int t = 0; t < 256; t++) {
        float a = attnw[t][s];
        float4 v0 = vb[t * 64 + g * 2];
        float4 v1 = vb[t * 64 + g * 2 + 1];
        A0.x += a * v0.x; A0.y += a * v0.y; A0.z += a * v0.z; A0.w += a * v0.w;
        A1.x += a * v1.x; A1.y += a * v1.y; A1.z += a * v1.z; A1.w += a * v1.w;
    }
    float4* op = (float4*)(g_updp + ((b * 16 + chunk) * 8 + s) * 256 + g * 8);
    op[0] = A0; op[1] = A1;
}

// =================================================================================
// K5: reduce partials over 16 chunks, divide by colsum.  grid 64, 256 threads.
// =================================================================================
__global__ void __launch_bounds__(256) k5_reduce()
{
    int tid = threadIdx.x, b = blockIdx.x;
    int s = tid >> 5, g = tid & 31;
    float c = (g < 16) ? g_colp[(b * 16 + g) * 8 + s] : 0.f;
#pragma unroll
    for (int off = 16; off >= 1; off >>= 1)
        c += __shfl_xor_sync(0xffffffffu, c, off);
    float4 A0 = make_float4(0,0,0,0), A1 = make_float4(0,0,0,0);
    for (int ch = 0; ch < 16; ch++) {
        const float4* p = (const float4*)(g_updp + ((b * 16 + ch) * 8 + s) * 256 + g * 8);
        float4 u0 = p[0], u1 = p[1];
        A0.x += u0.x; A0.y += u0.y; A0.z += u0.z; A0.w += u0.w;
        A1.x += u1.x; A1.y += u1.y; A1.z += u1.z; A1.w += u1.w;
    }
    float inv = 1.0f / c;
    A0.x *= inv; A0.y *= inv; A0.z *= inv; A0.w *= inv;
    A1.x *= inv; A1.y *= inv; A1.z *= inv; A1.w *= inv;
    float4* o = (float4*)(g_upd + (b * 8 + s) * 256 + g * 8);
    o[0] = A0; o[1] = A1;
}

// =================================================================================
// K6: GRU + LN + MLP, fused per batch.  grid 64, 256 threads, 96 KB dyn smem.
// =================================================================================
__global__ void __launch_bounds__(256) k6_gru_mlp(
    const float* __restrict__ w_ih, const float* __restrict__ w_hh,
    const float* __restrict__ b_ih, const float* __restrict__ b_hh,
    const float* __restrict__ w1,  const float* __restrict__ b1,
    const float* __restrict__ w2,  const float* __restrict__ b2,
    const float* __restrict__ lnw, const float* __restrict__ lnb,
    float* out2)
{
    extern __shared__ float sm[];
    float* up = sm;               // [8][256]
    float* hp = sm + 2048;        // [8][256]
    float* gi = sm + 4096;        // [8][768]
    float* gh = sm + 10240;       // [8][768]
    float* ns = sm + 16384;       // [8][256]
    float* sn = sm + 18432;       // [8][256]
    float* h1 = sm + 20480;       // [8][512]
    int tid = threadIdx.x, b = blockIdx.x;

    for (int i = tid; i < 2048; i += 256) {
        up[i] = g_upd[b * 2048 + i];
        hp[i] = g_slots[b * 2048 + i];
    }
    __syncthreads();

    const float4* up4 = (const float4*)up;
    const float4* hp4 = (const float4*)hp;
    for (int m = 0; m < 3; m++) {
        int o = m * 256 + tid;
        float ai[8] = {0,0,0,0,0,0,0,0};
        float ah[8] = {0,0,0,0,0,0,0,0};
        const float4* wi = (const float4*)(w_ih + o * 256);
        const float4* wh = (const float4*)(w_hh + o * 256);
        for (int d4 = 0; d4 < 64; d4++) {
            float4 a = wi[d4];
            float4 cH = wh[d4];
#pragma unroll
            for (int r = 0; r < 8; r++) {
                float4 u = up4[r * 64 + d4];
                float4 h = hp4[r * 64 + d4];
                ai[r] += a.x*u.x + a.y*u.y + a.z*u.z + a.w*u.w;
                ah[r] += cH.x*h.x + cH.y*h.y + cH.z*h.z + cH.w*h.w;
            }
        }
        float bi = b_ih[o], bh = b_hh[o];
#pragma unroll
        for (int r = 0; r < 8; r++) {
            gi[r * 768 + o] = ai[r] + bi;
            gh[r * 768 + o] = ah[r] + bh;
        }
    }
    __syncthreads();

    for (int j = 0; j < 8; j++) {          // gates: row j, dim tid
        int r = j, d = tid;
        float ir = gi[r*768 + d],       hr = gh[r*768 + d];
        float iz = gi[r*768 + 256 + d], hz = gh[r*768 + 256 + d];
        float in_ = gi[r*768 + 512 + d], hn = gh[r*768 + 512 + d];
        float rg = 1.0f / (1.0f + expf(-(ir + hr)));
        float zg = 1.0f / (1.0f + expf(-(iz + hz)));
        float ng = tanhf(in_ + rg * hn);
        ns[r*256 + d] = (1.0f - zg) * ng + zg * hp[r*256 + d];
    }
    __syncthreads();

    {   // LN(ns) per row, warp per row
        int r = tid >> 5, l = tid & 31;
        const float4* nr = (const float4*)(ns + r * 256);
        float4 v0 = nr[l * 2], v1 = nr[l * 2 + 1];
        float s1 = v0.x + v0.y + v0.z + v0.w + v1.x + v1.y + v1.z + v1.w;
        float s2 = v0.x*v0.x + v0.y*v0.y + v0.z*v0.z + v0.w*v0.w
                 + v1.x*v1.x + v1.y*v1.y + v1.z*v1.z + v1.w*v1.w;
#pragma unroll
        for (int off = 16; off >= 1; off >>= 1) {
            s1 += __shfl_xor_sync(0xffffffffu, s1, off);
            s2 += __shfl_xor_sync(0xffffffffu, s2, off);
        }
        float mean = s1 * (1.0f / 256.0f);
        float var  = s2 * (1.0f / 256.0f) - mean * mean;
        float rs   = rsqrtf(var + 1e-5f);
        int d0 = l * 8;
        sn[r*256 + d0 + 0] = (v0.x - mean) * rs * lnw[d0+0] + lnb[d0+0];
        sn[r*256 + d0 + 1] = (v0.y - mean) * rs * lnw[d0+1] + lnb[d0+1];
        sn[r*256 + d0 + 2] = (v0.z - mean) * rs * lnw[d0+2] + lnb[d0+2];
        sn[r*256 + d0 + 3] = (v0.w - mean) * rs * lnw[d0+3] + lnb[d0+3];
        sn[r*256 + d0 + 4] = (v1.x - mean) * rs * lnw[d0+4] + lnb[d0+4];
        sn[r*256 + d0 + 5] = (v1.y - mean) * rs * lnw[d0+5] + lnb[d0+5];
        sn[r*256 + d0 + 6] = (v1.z - mean) * rs * lnw[d0+6] + lnb[d0+6];
        sn[r*256 + d0 + 7] = (v1.w - mean) * rs * lnw[d0+7] + lnb[d0+7];
    }
    __syncthreads();

    const float4* sn4 = (const float4*)sn;
    for (int m = 0; m < 2; m++) {          // h1 = relu(sn @ w1^T + b1)
        int o = m * 256 + tid;
        float a[8] = {0,0,0,0,0,0,0,0};
        const float4* wr = (const float4*)(w1 + o * 256);
        for (int d4 = 0; d4 < 64; d4++) {
            float4 wv = wr[d4];
#pragma unroll
            for (int r = 0; r < 8; r++) {
                float4 s = sn4[r * 64 + d4];
                a[r] += wv.x*s.x + wv.y*s.y + wv.z*s.z + wv.w*s.w;
            }
        }
        float bb = b1[o];
#pragma unroll
        for (int r = 0; r < 8; r++) h1[r * 512 + o] = fmaxf(a[r] + bb, 0.0f);
    }
    __syncthreads();

    const float4* h14 = (const float4*)h1;
    {   // out = ns + h1 @ w2^T + b2
        int o = tid;
        float a[8] = {0,0,0,0,0,0,0,0};
        const float4* wr = (const float4*)(w2 + o * 512);
        for (int d4 = 0; d4 < 128; d4++) {
            float4 wv = wr[d4];
#pragma unroll
            for (int r = 0; r < 8; r++) {
                float4 h = h14[r * 128 + d4];
                a[r] += wv.x*h.x + wv.y*h.y + wv.z*h.z + wv.w*h.w;
            }
        }
        float bb = b2[o];
#pragma unroll
        for (int r = 0; r < 8; r++) {
            float vout = ns[r * 256 + o] + a[r] + bb;
            g_slots[(b * 8 + r) * 256 + o] = vout;
            if (out2) out2[(b * 8 + r) * 256 + o] = vout;
        }
    }
}

// =================================================================================
extern "C" void kernel_launch(void* const* d_in, const int* in_sizes, int n_in,
                              void* d_out, int out_size) {
    const float* inputs  = (const float*)d_in[0];
    const float* noise   = (const float*)d_in[1];
    const float* ln_in_w = (const float*)d_in[2];
    const float* ln_in_b = (const float*)d_in[3];
    const float* ln_sl_w = (const float*)d_in[4];
    const float* ln_sl_b = (const float*)d_in[5];
    const float* ln_ml_w = (const float*)d_in[6];
    const float* ln_ml_b = (const float*)d_in[7];
    const float* mu      = (const float*)d_in[8];
    const float* ls      = (const float*)d_in[9];
    const float* Wq      = (const float*)d_in[10];
    const float* Wk      = (const float*)d_in[11];
    const float* Wv      = (const float*)d_in[12];
    const float* w_ih    = (const float*)d_in[13];
    const float* w_hh    = (const float*)d_in[14];
    const float* b_ih    = (const float*)d_in[15];
    const float* b_hh    = (const float*)d_in[16];
    const float* w1      = (const float*)d_in[17];
    const float* b1      = (const float*)d_in[18];
    const float* w2      = (const float*)d_in[19];
    const float* b2      = (const float*)d_in[20];
    float* out = (float*)d_out;

    cudaFuncSetAttribute(k1_proj, cudaFuncAttributeMaxDynamicSharedMemorySize, 100608);
    cudaFuncSetAttribute(k6_gru_mlp, cudaFuncAttributeMaxDynamicSharedMemorySize, 98304);

    k0_init<<<512, 256>>>(noise, mu, ls);
    k1_proj<<<dim3(4096, 2), 256, 100608>>>(inputs, Wk, Wv, ln_in_w, ln_in_b);
    for (int it = 0; it < 3; it++) {
        k3_q<<<64, 256>>>(Wq, ln_sl_w, ln_sl_b);
        k4_attn<<<dim3(16, 64), 256>>>();
        k5_reduce<<<64, 256>>>();
        k6_gru_mlp<<<64, 256, 98304>>>(w_ih, w_hh, b_ih, b_hh, w1, b1, w2, b2,
                                       ln_ml_w, ln_ml_b, (it == 2) ? out : nullptr);
    }
}

// round 3
// speedup vs baseline: 1.3634x; 1.3634x over previous
#include <cuda_runtime.h>

#define B_ 64
#define N_ 4096
#define D_ 256
#define S_ 8
#define H_ 512
#define CHUNKS 16

// ---------------- scratch (device globals; no allocation allowed) ----------------
__device__ float g_k[B_*N_*D_];            // 256 MB
__device__ float g_v[B_*N_*D_];            // 256 MB
__device__ float g_slots[B_*S_*D_];
__device__ float g_q[B_*S_*D_];
__device__ float g_upd[B_*S_*D_];
__device__ float g_updp[B_*CHUNKS*S_*D_];  // partials
__device__ float g_colp[B_*CHUNKS*S_];

// ---------------- helpers --------------------------------------------------------
__device__ __forceinline__ unsigned long long pack2(float lo, float hi) {
    unsigned long long r;
    asm("mov.b64 %0, {%1, %2};" : "=l"(r) : "f"(lo), "f"(hi));
    return r;
}
__device__ __forceinline__ unsigned long long ffma2(unsigned long long a,
                                                    unsigned long long b,
                                                    unsigned long long c) {
    unsigned long long d;
    asm("fma.rn.f32x2 %0, %1, %2, %3;" : "=l"(d) : "l"(a), "l"(b), "l"(c));
    return d;
}
__device__ __forceinline__ float2 unpack2(unsigned long long v) {
    float lo, hi;
    asm("mov.b64 {%0, %1}, %2;" : "=f"(lo), "=f"(hi) : "l"(v));
    return make_float2(lo, hi);
}
__device__ __forceinline__ unsigned int f2tf32(float f) {
    unsigned int o;
    asm("cvt.rna.tf32.f32 %0, %1;" : "=r"(o) : "f"(f));
    return o;
}
__device__ __forceinline__ void mma_tf32(float& c0, float& c1, float& c2, float& c3,
                                         unsigned a0, unsigned a1, unsigned a2, unsigned a3,
                                         unsigned b0, unsigned b1) {
    asm volatile(
        "mma.sync.aligned.m16n8k8.row.col.f32.tf32.tf32.f32 "
        "{%0,%1,%2,%3}, {%4,%5,%6,%7}, {%8,%9}, {%0,%1,%2,%3};"
        : "+f"(c0), "+f"(c1), "+f"(c2), "+f"(c3)
        : "r"(a0), "r"(a1), "r"(a2), "r"(a3), "r"(b0), "r"(b1));
}

// =================================================================================
// K0: slots = mu + exp(log_sigma) * noise
// =================================================================================
__global__ void k0_init(const float* __restrict__ noise,
                        const float* __restrict__ mu,
                        const float* __restrict__ ls) {
    int i = blockIdx.x * 256 + threadIdx.x;
    int d = i & 255;
    g_slots[i] = mu[d] + expf(ls[d]) * noise[i];
}

// =================================================================================
// K1: fused LayerNorm + k/v projection via tf32 mma.sync.
// grid (2048, 2): x = 128-token tile, y selects Wk/Wv. 256 threads.
// smem: xs[128][260] (tf32 bits of LN(x)), wsT[32][264] (W chunk transposed tf32)
// =================================================================================
#define XS_STR 260
#define WS_STR 264
#define K1_SMEM ((128*XS_STR + 32*WS_STR) * 4)

__global__ void __launch_bounds__(256, 1) k1_proj(
    const float* __restrict__ inp, const float* __restrict__ Wk,
    const float* __restrict__ Wv, const float* __restrict__ lnw,
    const float* __restrict__ lnb)
{
    extern __shared__ float sm[];
    float* xs = sm;                              // [128][260] tf32 bits
    float* wsT = sm + 128 * XS_STR;              // [32][264] tf32 bits
    unsigned* xs_u = (unsigned*)xs;
    unsigned* ws_u = (unsigned*)wsT;

    int tid = threadIdx.x;
    const float* W = (blockIdx.y == 0) ? Wk : Wv;
    float* outp = (blockIdx.y == 0) ? g_k : g_v;
    long tok0 = (long)blockIdx.x * 128;

    // ---- LN: 2 threads per token, 128 dims each ----
    {
        int tok = tid >> 1, half = tid & 1;
        const float4* xr = (const float4*)(inp + (tok0 + tok) * 256 + half * 128);
        float* xw = xs + tok * XS_STR + half * 128;
        float s1 = 0.f, s2 = 0.f;
#pragma unroll
        for (int j = 0; j < 32; j++) {
            float4 t = xr[j];
            s1 += t.x + t.y + t.z + t.w;
            s2 += t.x*t.x + t.y*t.y + t.z*t.z + t.w*t.w;
            *(float4*)(xw + j * 4) = t;
        }
        s1 += __shfl_xor_sync(0xffffffffu, s1, 1);
        s2 += __shfl_xor_sync(0xffffffffu, s2, 1);
        float mean = s1 * (1.0f / 256.0f);
        float var  = s2 * (1.0f / 256.0f) - mean * mean;
        float rs   = rsqrtf(var + 1e-5f);
        const float4* lw4 = (const float4*)(lnw + half * 128);
        const float4* lb4 = (const float4*)(lnb + half * 128);
        unsigned* xu = (unsigned*)xw;
#pragma unroll
        for (int j = 0; j < 32; j++) {
            float4 t = *(float4*)(xw + j * 4);
            float4 w4 = __ldg(lw4 + j);
            float4 b4 = __ldg(lb4 + j);
            xu[j*4+0] = f2tf32((t.x - mean) * rs * w4.x + b4.x);
            xu[j*4+1] = f2tf32((t.y - mean) * rs * w4.y + b4.y);
            xu[j*4+2] = f2tf32((t.z - mean) * rs * w4.z + b4.z);
            xu[j*4+3] = f2tf32((t.w - mean) * rs * w4.w + b4.w);
        }
    }

    // ---- GEMM: warps 2x4, warp tile = 64 tokens x 64 outdims ----
    int w = tid >> 5, lane = tid & 31;
    int m0 = (w >> 2) * 64, n0 = (w & 3) * 64;
    int g = lane >> 2, c = lane & 3;

    float acc[4][8][4];
#pragma unroll
    for (int mt = 0; mt < 4; mt++)
#pragma unroll
        for (int nt = 0; nt < 8; nt++)
#pragma unroll
            for (int e = 0; e < 4; e++) acc[mt][nt][e] = 0.f;

    for (int kc = 0; kc < 256; kc += 32) {
        __syncthreads();
        {   // stage W[tid][kc..kc+31] transposed (tf32) -> wsT[kk][tid]
            const float4* wr = (const float4*)(W + tid * 256 + kc);
#pragma unroll
            for (int j = 0; j < 8; j++) {
                float4 w4 = wr[j];
                ws_u[(4*j+0) * WS_STR + tid] = f2tf32(w4.x);
                ws_u[(4*j+1) * WS_STR + tid] = f2tf32(w4.y);
                ws_u[(4*j+2) * WS_STR + tid] = f2tf32(w4.z);
                ws_u[(4*j+3) * WS_STR + tid] = f2tf32(w4.w);
            }
        }
        __syncthreads();
#pragma unroll
        for (int ks = 0; ks < 4; ks++) {
            int k0 = ks * 8;
            unsigned a[4][4];
#pragma unroll
            for (int mt = 0; mt < 4; mt++) {
                int rb = (m0 + mt * 16 + g) * XS_STR + kc + k0 + c;
                a[mt][0] = xs_u[rb];
                a[mt][1] = xs_u[rb + 8 * XS_STR];
                a[mt][2] = xs_u[rb + 4];
                a[mt][3] = xs_u[rb + 8 * XS_STR + 4];
            }
            unsigned b[8][2];
#pragma unroll
            for (int nt = 0; nt < 8; nt++) {
                int cb = (k0 + c) * WS_STR + n0 + nt * 8 + g;
                b[nt][0] = ws_u[cb];
                b[nt][1] = ws_u[cb + 4 * WS_STR];
            }
#pragma unroll
            for (int mt = 0; mt < 4; mt++)
#pragma unroll
                for (int nt = 0; nt < 8; nt++)
                    mma_tf32(acc[mt][nt][0], acc[mt][nt][1],
                             acc[mt][nt][2], acc[mt][nt][3],
                             a[mt][0], a[mt][1], a[mt][2], a[mt][3],
                             b[nt][0], b[nt][1]);
        }
    }
    // store
#pragma unroll
    for (int mt = 0; mt < 4; mt++) {
        long r0 = tok0 + m0 + mt * 16 + g;
#pragma unroll
        for (int nt = 0; nt < 8; nt++) {
            int col = n0 + nt * 8 + c * 2;
            *(float2*)(outp + r0 * 256 + col) = make_float2(acc[mt][nt][0], acc[mt][nt][1]);
            *(float2*)(outp + (r0 + 8) * 256 + col) = make_float2(acc[mt][nt][2], acc[mt][nt][3]);
        }
    }
}

// =================================================================================
// K3: q = LN(slots) @ Wq^T * scale.  grid 64 (batch), 256 threads. (fp32)
// =================================================================================
__global__ void __launch_bounds__(256) k3_q(
    const float* __restrict__ Wq, const float* __restrict__ lnw,
    const float* __restrict__ lnb)
{
    __shared__ float sn[8 * 256];
    int tid = threadIdx.x, b = blockIdx.x;
    int r = tid >> 5, l = tid & 31;

    const float4* sr = (const float4*)(g_slots + (b * 8 + r) * 256);
    float4 v0 = sr[l * 2], v1 = sr[l * 2 + 1];
    float s1 = v0.x + v0.y + v0.z + v0.w + v1.x + v1.y + v1.z + v1.w;
    float s2 = v0.x*v0.x + v0.y*v0.y + v0.z*v0.z + v0.w*v0.w
             + v1.x*v1.x + v1.y*v1.y + v1.z*v1.z + v1.w*v1.w;
#pragma unroll
    for (int off = 16; off >= 1; off >>= 1) {
        s1 += __shfl_xor_sync(0xffffffffu, s1, off);
        s2 += __shfl_xor_sync(0xffffffffu, s2, off);
    }
    float mean = s1 * (1.0f / 256.0f);
    float var  = s2 * (1.0f / 256.0f) - mean * mean;
    float rs   = rsqrtf(var + 1e-5f);
    int d0 = l * 8;
    sn[r*256 + d0 + 0] = (v0.x - mean) * rs * lnw[d0+0] + lnb[d0+0];
    sn[r*256 + d0 + 1] = (v0.y - mean) * rs * lnw[d0+1] + lnb[d0+1];
    sn[r*256 + d0 + 2] = (v0.z - mean) * rs * lnw[d0+2] + lnb[d0+2];
    sn[r*256 + d0 + 3] = (v0.w - mean) * rs * lnw[d0+3] + lnb[d0+3];
    sn[r*256 + d0 + 4] = (v1.x - mean) * rs * lnw[d0+4] + lnb[d0+4];
    sn[r*256 + d0 + 5] = (v1.y - mean) * rs * lnw[d0+5] + lnb[d0+5];
    sn[r*256 + d0 + 6] = (v1.z - mean) * rs * lnw[d0+6] + lnb[d0+6];
    sn[r*256 + d0 + 7] = (v1.w - mean) * rs * lnw[d0+7] + lnb[d0+7];
    __syncthreads();

    float acc[8] = {0,0,0,0,0,0,0,0};
    const float4* wr  = (const float4*)(Wq + tid * 256);
    const float4* sn4 = (const float4*)sn;
    for (int d4 = 0; d4 < 64; d4++) {
        float4 w = wr[d4];
#pragma unroll
        for (int rr = 0; rr < 8; rr++) {
            float4 s = sn4[rr * 64 + d4];
            acc[rr] += w.x*s.x + w.y*s.y + w.z*s.z + w.w*s.w;
        }
    }
    const float scale = 0.0625f;
#pragma unroll
    for (int rr = 0; rr < 8; rr++)
        g_q[(b * 8 + rr) * 256 + tid] = acc[rr] * scale;
}

// =================================================================================
// K4: fused logits + softmax(+eps) + unnormalized updates, per 256-token chunk.
// grid (16, 64), 256 threads.  Phase 1: lane = (tok%4)*8 + dimgroup, 8-lane reduce.
// =================================================================================
__global__ void __launch_bounds__(256) k4_attn()
{
    __shared__ __align__(16) float qg[8 * 260];   // q regrouped per dimgroup (+pad 4)
    __shared__ float attnw[256 * 9];              // stride 9 (bank-friendly)
    int tid = threadIdx.x;
    int b = blockIdx.y, chunk = blockIdx.x;
    long tok0 = (long)b * 4096 + (long)chunk * 256;

    // stage q: qg[dg*260 + jj*8 + s] = q[s][dg*32 + jj]
    for (int i = tid; i < 2048; i += 256) {
        int s = i >> 8, d = i & 255;
        qg[(d >> 5) * 260 + (d & 31) * 8 + s] = g_q[b * 2048 + i];
    }
    __syncthreads();

    int w = tid >> 5, lane = tid & 31;
    int t = lane >> 3, dg = lane & 7;

    for (int p = 0; p < 8; p++) {
        int tk = w * 32 + p * 4 + t;               // local token
        const float4* kr = (const float4*)(g_k + (tok0 + tk) * 256 + dg * 32);
        const ulonglong2* qp = (const ulonglong2*)(qg + dg * 260);
        unsigned long long a01 = 0, a23 = 0, a45 = 0, a67 = 0;
#pragma unroll
        for (int j = 0; j < 8; j++) {
            float4 kv = kr[j];
#pragma unroll
            for (int e = 0; e < 4; e++) {
                int jj = j * 4 + e;
                float kd = (e == 0) ? kv.x : (e == 1) ? kv.y : (e == 2) ? kv.z : kv.w;
                unsigned long long kp = pack2(kd, kd);
                ulonglong2 qa = qp[jj * 2];
                ulonglong2 qb = qp[jj * 2 + 1];
                a01 = ffma2(kp, qa.x, a01);
                a23 = ffma2(kp, qa.y, a23);
                a45 = ffma2(kp, qb.x, a45);
                a67 = ffma2(kp, qb.y, a67);
            }
        }
        float pz[8];
        { float2 u = unpack2(a01); pz[0] = u.x; pz[1] = u.y; }
        { float2 u = unpack2(a23); pz[2] = u.x; pz[3] = u.y; }
        { float2 u = unpack2(a45); pz[4] = u.x; pz[5] = u.y; }
        { float2 u = unpack2(a67); pz[6] = u.x; pz[7] = u.y; }
#pragma unroll
        for (int off = 1; off <= 4; off <<= 1)
#pragma unroll
            for (int s = 0; s < 8; s++)
                pz[s] += __shfl_xor_sync(0xffffffffu, pz[s], off);
        if (dg == 0) {
            float mx = pz[0];
#pragma unroll
            for (int s = 1; s < 8; s++) mx = fmaxf(mx, pz[s]);
            float e[8], se = 0.f;
#pragma unroll
            for (int s = 0; s < 8; s++) { e[s] = expf(pz[s] - mx); se += e[s]; }
            float inv = 1.0f / se;
#pragma unroll
            for (int s = 0; s < 8; s++) attnw[tk * 9 + s] = e[s] * inv + 1e-8f;
        }
    }
    __syncthreads();

    // column sums: warp w handles slot w
    {
        float csum = 0.f;
#pragma unroll
        for (int i = 0; i < 8; i++) csum += attnw[(lane + 32 * i) * 9 + w];
#pragma unroll
        for (int off = 16; off >= 1; off >>= 1)
            csum += __shfl_xor_sync(0xffffffffu, csum, off);
        if (lane == 0) g_colp[(b * 16 + chunk) * 8 + w] = csum;
    }

    // phase 2: updates partial.  warp = slot, lane = 8-dim group.
    int s = w, g = lane;
    float4 A0 = make_float4(0,0,0,0), A1 = make_float4(0,0,0,0);
    const float4* vb = (const float4*)(g_v + tok0 * 256);
#pragma unroll 4
    for (int tt = 0; tt < 256; tt++) {
        float a = attnw[tt * 9 + s];
        float4 v0 = vb[tt * 64 + g * 2];
        float4 v1 = vb[tt * 64 + g * 2 + 1];
        A0.x += a * v0.x; A0.y += a * v0.y; A0.z += a * v0.z; A0.w += a * v0.w;
        A1.x += a * v1.x; A1.y += a * v1.y; A1.z += a * v1.z; A1.w += a * v1.w;
    }
    float4* op = (float4*)(g_updp + ((b * 16 + chunk) * 8 + s) * 256 + g * 8);
    op[0] = A0; op[1] = A1;
}

// =================================================================================
// K5: reduce partials over 16 chunks, divide by colsum.  grid 64, 256 threads.
// =================================================================================
__global__ void __launch_bounds__(256) k5_reduce()
{
    int tid = threadIdx.x, b = blockIdx.x;
    int s = tid >> 5, g = tid & 31;
    float c = (g < 16) ? g_colp[(b * 16 + g) * 8 + s] : 0.f;
#pragma unroll
    for (int off = 16; off >= 1; off >>= 1)
        c += __shfl_xor_sync(0xffffffffu, c, off);
    float4 A0 = make_float4(0,0,0,0), A1 = make_float4(0,0,0,0);
    for (int ch = 0; ch < 16; ch++) {
        const float4* p = (const float4*)(g_updp + ((b * 16 + ch) * 8 + s) * 256 + g * 8);
        float4 u0 = p[0], u1 = p[1];
        A0.x += u0.x; A0.y += u0.y; A0.z += u0.z; A0.w += u0.w;
        A1.x += u1.x; A1.y += u1.y; A1.z += u1.z; A1.w += u1.w;
    }
    float inv = 1.0f / c;
    A0.x *= inv; A0.y *= inv; A0.z *= inv; A0.w *= inv;
    A1.x *= inv; A1.y *= inv; A1.z *= inv; A1.w *= inv;
    float4* o = (float4*)(g_upd + (b * 8 + s) * 256 + g * 8);
    o[0] = A0; o[1] = A1;
}

// =================================================================================
// K6: GRU + LN + MLP, fused per batch.  grid 64, 256 threads, 96 KB dyn smem.
// =================================================================================
__global__ void __launch_bounds__(256) k6_gru_mlp(
    const float* __restrict__ w_ih, const float* __restrict__ w_hh,
    const float* __restrict__ b_ih, const float* __restrict__ b_hh,
    const float* __restrict__ w1,  const float* __restrict__ b1,
    const float* __restrict__ w2,  const float* __restrict__ b2,
    const float* __restrict__ lnw, const float* __restrict__ lnb,
    float* out2)
{
    extern __shared__ float sm[];
    float* up = sm;               // [8][256]
    float* hp = sm + 2048;        // [8][256]
    float* gi = sm + 4096;        // [8][768]
    float* gh = sm + 10240;       // [8][768]
    float* ns = sm + 16384;       // [8][256]
    float* sn = sm + 18432;       // [8][256]
    float* h1 = sm + 20480;       // [8][512]
    int tid = threadIdx.x, b = blockIdx.x;

    for (int i = tid; i < 2048; i += 256) {
        up[i] = g_upd[b * 2048 + i];
        hp[i] = g_slots[b * 2048 + i];
    }
    __syncthreads();

    const float4* up4 = (const float4*)up;
    const float4* hp4 = (const float4*)hp;
    for (int m = 0; m < 3; m++) {
        int o = m * 256 + tid;
        float ai[8] = {0,0,0,0,0,0,0,0};
        float ah[8] = {0,0,0,0,0,0,0,0};
        const float4* wi = (const float4*)(w_ih + o * 256);
        const float4* wh = (const float4*)(w_hh + o * 256);
        for (int d4 = 0; d4 < 64; d4++) {
            float4 a = wi[d4];
            float4 cH = wh[d4];
#pragma unroll
            for (int r = 0; r < 8; r++) {
                float4 u = up4[r * 64 + d4];
                float4 h = hp4[r * 64 + d4];
                ai[r] += a.x*u.x + a.y*u.y + a.z*u.z + a.w*u.w;
                ah[r] += cH.x*h.x + cH.y*h.y + cH.z*h.z + cH.w*h.w;
            }
        }
        float bi = b_ih[o], bh = b_hh[o];
#pragma unroll
        for (int r = 0; r < 8; r++) {
            gi[r * 768 + o] = ai[r] + bi;
            gh[r * 768 + o] = ah[r] + bh;
        }
    }
    __syncthreads();

    for (int j = 0; j < 8; j++) {
        int r = j, d = tid;
        float ir = gi[r*768 + d],       hr = gh[r*768 + d];
        float iz = gi[r*768 + 256 + d], hz = gh[r*768 + 256 + d];
        float in_ = gi[r*768 + 512 + d], hn = gh[r*768 + 512 + d];
        float rg = 1.0f / (1.0f + expf(-(ir + hr)));
        float zg = 1.0f / (1.0f + expf(-(iz + hz)));
        float ng = tanhf(in_ + rg * hn);
        ns[r*256 + d] = (1.0f - zg) * ng + zg * hp[r*256 + d];
    }
    __syncthreads();

    {   // LN(ns) per row, warp per row
        int r = tid >> 5, l = tid & 31;
        const float4* nr = (const float4*)(ns + r * 256);
        float4 v0 = nr[l * 2], v1 = nr[l * 2 + 1];
        float s1 = v0.x + v0.y + v0.z + v0.w + v1.x + v1.y + v1.z + v1.w;
        float s2 = v0.x*v0.x + v0.y*v0.y + v0.z*v0.z + v0.w*v0.w
                 + v1.x*v1.x + v1.y*v1.y + v1.z*v1.z + v1.w*v1.w;
#pragma unroll
        for (int off = 16; off >= 1; off >>= 1) {
            s1 += __shfl_xor_sync(0xffffffffu, s1, off);
            s2 += __shfl_xor_sync(0xffffffffu, s2, off);
        }
        float mean = s1 * (1.0f / 256.0f);
        float var  = s2 * (1.0f / 256.0f) - mean * mean;
        float rs   = rsqrtf(var + 1e-5f);
        int d0 = l * 8;
        sn[r*256 + d0 + 0] = (v0.x - mean) * rs * lnw[d0+0] + lnb[d0+0];
        sn[r*256 + d0 + 1] = (v0.y - mean) * rs * lnw[d0+1] + lnb[d0+1];
        sn[r*256 + d0 + 2] = (v0.z - mean) * rs * lnw[d0+2] + lnb[d0+2];
        sn[r*256 + d0 + 3] = (v0.w - mean) * rs * lnw[d0+3] + lnb[d0+3];
        sn[r*256 + d0 + 4] = (v1.x - mean) * rs * lnw[d0+4] + lnb[d0+4];
        sn[r*256 + d0 + 5] = (v1.y - mean) * rs * lnw[d0+5] + lnb[d0+5];
        sn[r*256 + d0 + 6] = (v1.z - mean) * rs * lnw[d0+6] + lnb[d0+6];
        sn[r*256 + d0 + 7] = (v1.w - mean) * rs * lnw[d0+7] + lnb[d0+7];
    }
    __syncthreads();

    const float4* sn4 = (const float4*)sn;
    for (int m = 0; m < 2; m++) {
        int o = m * 256 + tid;
        float a[8] = {0,0,0,0,0,0,0,0};
        const float4* wr = (const float4*)(w1 + o * 256);
        for (int d4 = 0; d4 < 64; d4++) {
            float4 wv = wr[d4];
#pragma unroll
            for (int r = 0; r < 8; r++) {
                float4 s = sn4[r * 64 + d4];
                a[r] += wv.x*s.x + wv.y*s.y + wv.z*s.z + wv.w*s.w;
            }
        }
        float bb = b1[o];
#pragma unroll
        for (int r = 0; r < 8; r++) h1[r * 512 + o] = fmaxf(a[r] + bb, 0.0f);
    }
    __syncthreads();

    const float4* h14 = (const float4*)h1;
    {
        int o = tid;
        float a[8] = {0,0,0,0,0,0,0,0};
        const float4* wr = (const float4*)(w2 + o * 512);
        for (int d4 = 0; d4 < 128; d4++) {
            float4 wv = wr[d4];
#pragma unroll
            for (int r = 0; r < 8; r++) {
                float4 h = h14[r * 128 + d4];
                a[r] += wv.x*h.x + wv.y*h.y + wv.z*h.z + wv.w*h.w;
            }
        }
        float bb = b2[o];
#pragma unroll
        for (int r = 0; r < 8; r++) {
            float vout = ns[r * 256 + o] + a[r] + bb;
            g_slots[(b * 8 + r) * 256 + o] = vout;
            if (out2) out2[(b * 8 + r) * 256 + o] = vout;
        }
    }
}

// =================================================================================
extern "C" void kernel_launch(void* const* d_in, const int* in_sizes, int n_in,
                              void* d_out, int out_size) {
    const float* inputs  = (const float*)d_in[0];
    const float* noise   = (const float*)d_in[1];
    const float* ln_in_w = (const float*)d_in[2];
    const float* ln_in_b = (const float*)d_in[3];
    const float* ln_sl_w = (const float*)d_in[4];
    const float* ln_sl_b = (const float*)d_in[5];
    const float* ln_ml_w = (const float*)d_in[6];
    const float* ln_ml_b = (const float*)d_in[7];
    const float* mu      = (const float*)d_in[8];
    const float* ls      = (const float*)d_in[9];
    const float* Wq      = (const float*)d_in[10];
    const float* Wk      = (const float*)d_in[11];
    const float* Wv      = (const float*)d_in[12];
    const float* w_ih    = (const float*)d_in[13];
    const float* w_hh    = (const float*)d_in[14];
    const float* b_ih    = (const float*)d_in[15];
    const float* b_hh    = (const float*)d_in[16];
    const float* w1      = (const float*)d_in[17];
    const float* b1      = (const float*)d_in[18];
    const float* w2      = (const float*)d_in[19];
    const float* b2      = (const float*)d_in[20];
    float* out = (float*)d_out;

    cudaFuncSetAttribute(k1_proj, cudaFuncAttributeMaxDynamicSharedMemorySize, K1_SMEM);
    cudaFuncSetAttribute(k6_gru_mlp, cudaFuncAttributeMaxDynamicSharedMemorySize, 98304);

    k0_init<<<512, 256>>>(noise, mu, ls);
    k1_proj<<<dim3(2048, 2), 256, K1_SMEM>>>(inputs, Wk, Wv, ln_in_w, ln_in_b);
    for (int it = 0; it < 3; it++) {
        k3_q<<<64, 256>>>(Wq, ln_sl_w, ln_sl_b);
        k4_attn<<<dim3(16, 64), 256>>>();
        k5_reduce<<<64, 256>>>();
        k6_gru_mlp<<<64, 256, 98304>>>(w_ih, w_hh, b_ih, b_hh, w1, b1, w2, b2,
                                       ln_ml_w, ln_ml_b, (it == 2) ? out : nullptr);
    }
}

// round 4
// speedup vs baseline: 1.7437x; 1.2789x over previous
#include <cuda_runtime.h>

#define B_ 64
#define N_ 4096
#define D_ 256
#define S_ 8
#define H_ 512
#define CH_ 32

// ---------------- scratch (device globals; no allocation allowed) ----------------
__device__ float g_k[B_*N_*D_];
__device__ float g_v[B_*N_*D_];
__device__ float g_slots[B_*S_*D_];
__device__ float g_q[B_*S_*D_];
__device__ float g_upd[B_*S_*D_];
__device__ float g_updp[B_*CH_*S_*D_];
__device__ float g_colp[B_*CH_*S_];
__device__ float g_gi[B_*S_*768];
__device__ float g_gh[B_*S_*768];
__device__ float g_ns[B_*S_*D_];
__device__ float g_sn[B_*S_*D_];
__device__ float g_h1[B_*S_*H_];

// ---------------- helpers --------------------------------------------------------
__device__ __forceinline__ unsigned int f2tf32(float f) {
    unsigned int o;
    asm("cvt.rna.tf32.f32 %0, %1;" : "=r"(o) : "f"(f));
    return o;
}
__device__ __forceinline__ void mma_tf32(float& c0, float& c1, float& c2, float& c3,
                                         unsigned a0, unsigned a1, unsigned a2, unsigned a3,
                                         unsigned b0, unsigned b1) {
    asm volatile(
        "mma.sync.aligned.m16n8k8.row.col.f32.tf32.tf32.f32 "
        "{%0,%1,%2,%3}, {%4,%5,%6,%7}, {%8,%9}, {%0,%1,%2,%3};"
        : "+f"(c0), "+f"(c1), "+f"(c2), "+f"(c3)
        : "r"(a0), "r"(a1), "r"(a2), "r"(a3), "r"(b0), "r"(b1));
}

// =================================================================================
// K0: slots = mu + exp(log_sigma) * noise
// =================================================================================
__global__ void k0_init(const float* __restrict__ noise,
                        const float* __restrict__ mu,
                        const float* __restrict__ ls) {
    int i = blockIdx.x * 256 + threadIdx.x;
    int d = i & 255;
    g_slots[i] = mu[d] + expf(ls[d]) * noise[i];
}

// =================================================================================
// K1: fused LayerNorm + k/v projection via tf32 mma (unchanged from R3).
// =================================================================================
#define XS_STR 260
#define WS_STR 264
#define K1_SMEM ((128*XS_STR + 32*WS_STR) * 4)

__global__ void __launch_bounds__(256, 1) k1_proj(
    const float* __restrict__ inp, const float* __restrict__ Wk,
    const float* __restrict__ Wv, const float* __restrict__ lnw,
    const float* __restrict__ lnb)
{
    extern __shared__ float sm[];
    float* xs = sm;
    float* wsT = sm + 128 * XS_STR;
    unsigned* xs_u = (unsigned*)xs;
    unsigned* ws_u = (unsigned*)wsT;

    int tid = threadIdx.x;
    const float* W = (blockIdx.y == 0) ? Wk : Wv;
    float* outp = (blockIdx.y == 0) ? g_k : g_v;
    long tok0 = (long)blockIdx.x * 128;

    {
        int tok = tid >> 1, half = tid & 1;
        const float4* xr = (const float4*)(inp + (tok0 + tok) * 256 + half * 128);
        float* xw = xs + tok * XS_STR + half * 128;
        float s1 = 0.f, s2 = 0.f;
#pragma unroll
        for (int j = 0; j < 32; j++) {
            float4 t = xr[j];
            s1 += t.x + t.y + t.z + t.w;
            s2 += t.x*t.x + t.y*t.y + t.z*t.z + t.w*t.w;
            *(float4*)(xw + j * 4) = t;
        }
        s1 += __shfl_xor_sync(0xffffffffu, s1, 1);
        s2 += __shfl_xor_sync(0xffffffffu, s2, 1);
        float mean = s1 * (1.0f / 256.0f);
        float var  = s2 * (1.0f / 256.0f) - mean * mean;
        float rs   = rsqrtf(var + 1e-5f);
        const float4* lw4 = (const float4*)(lnw + half * 128);
        const float4* lb4 = (const float4*)(lnb + half * 128);
        unsigned* xu = (unsigned*)xw;
#pragma unroll
        for (int j = 0; j < 32; j++) {
            float4 t = *(float4*)(xw + j * 4);
            float4 w4 = __ldg(lw4 + j);
            float4 b4 = __ldg(lb4 + j);
            xu[j*4+0] = f2tf32((t.x - mean) * rs * w4.x + b4.x);
            xu[j*4+1] = f2tf32((t.y - mean) * rs * w4.y + b4.y);
            xu[j*4+2] = f2tf32((t.z - mean) * rs * w4.z + b4.z);
            xu[j*4+3] = f2tf32((t.w - mean) * rs * w4.w + b4.w);
        }
    }

    int w = tid >> 5, lane = tid & 31;
    int m0 = (w >> 2) * 64, n0 = (w & 3) * 64;
    int g = lane >> 2, c = lane & 3;

    float acc[4][8][4];
#pragma unroll
    for (int mt = 0; mt < 4; mt++)
#pragma unroll
        for (int nt = 0; nt < 8; nt++)
#pragma unroll
            for (int e = 0; e < 4; e++) acc[mt][nt][e] = 0.f;

    for (int kc = 0; kc < 256; kc += 32) {
        __syncthreads();
        {
            const float4* wr = (const float4*)(W + tid * 256 + kc);
#pragma unroll
            for (int j = 0; j < 8; j++) {
                float4 w4 = wr[j];
                ws_u[(4*j+0) * WS_STR + tid] = f2tf32(w4.x);
                ws_u[(4*j+1) * WS_STR + tid] = f2tf32(w4.y);
                ws_u[(4*j+2) * WS_STR + tid] = f2tf32(w4.z);
                ws_u[(4*j+3) * WS_STR + tid] = f2tf32(w4.w);
            }
        }
        __syncthreads();
#pragma unroll
        for (int ks = 0; ks < 4; ks++) {
            int k0 = ks * 8;
            unsigned a[4][4];
#pragma unroll
            for (int mt = 0; mt < 4; mt++) {
                int rb = (m0 + mt * 16 + g) * XS_STR + kc + k0 + c;
                a[mt][0] = xs_u[rb];
                a[mt][1] = xs_u[rb + 8 * XS_STR];
                a[mt][2] = xs_u[rb + 4];
                a[mt][3] = xs_u[rb + 8 * XS_STR + 4];
            }
            unsigned b[8][2];
#pragma unroll
            for (int nt = 0; nt < 8; nt++) {
                int cb = (k0 + c) * WS_STR + n0 + nt * 8 + g;
                b[nt][0] = ws_u[cb];
                b[nt][1] = ws_u[cb + 4 * WS_STR];
            }
#pragma unroll
            for (int mt = 0; mt < 4; mt++)
#pragma unroll
                for (int nt = 0; nt < 8; nt++)
                    mma_tf32(acc[mt][nt][0], acc[mt][nt][1],
                             acc[mt][nt][2], acc[mt][nt][3],
                             a[mt][0], a[mt][1], a[mt][2], a[mt][3],
                             b[nt][0], b[nt][1]);
        }
    }
#pragma unroll
    for (int mt = 0; mt < 4; mt++) {
        long r0 = tok0 + m0 + mt * 16 + g;
#pragma unroll
        for (int nt = 0; nt < 8; nt++) {
            int col = n0 + nt * 8 + c * 2;
            *(float2*)(outp + r0 * 256 + col) = make_float2(acc[mt][nt][0], acc[mt][nt][1]);
            *(float2*)(outp + (r0 + 8) * 256 + col) = make_float2(acc[mt][nt][2], acc[mt][nt][3]);
        }
    }
}

// =================================================================================
// K3: q = LN(slots) @ Wq^T * scale.  grid 64, 256 threads.
// =================================================================================
__global__ void __launch_bounds__(256) k3_q(
    const float* __restrict__ Wq, const float* __restrict__ lnw,
    const float* __restrict__ lnb)
{
    __shared__ float sn[8 * 256];
    int tid = threadIdx.x, b = blockIdx.x;
    int r = tid >> 5, l = tid & 31;

    const float4* sr = (const float4*)(g_slots + (b * 8 + r) * 256);
    float4 v0 = sr[l * 2], v1 = sr[l * 2 + 1];
    float s1 = v0.x + v0.y + v0.z + v0.w + v1.x + v1.y + v1.z + v1.w;
    float s2 = v0.x*v0.x + v0.y*v0.y + v0.z*v0.z + v0.w*v0.w
             + v1.x*v1.x + v1.y*v1.y + v1.z*v1.z + v1.w*v1.w;
#pragma unroll
    for (int off = 16; off >= 1; off >>= 1) {
        s1 += __shfl_xor_sync(0xffffffffu, s1, off);
        s2 += __shfl_xor_sync(0xffffffffu, s2, off);
    }
    float mean = s1 * (1.0f / 256.0f);
    float var  = s2 * (1.0f / 256.0f) - mean * mean;
    float rs   = rsqrtf(var + 1e-5f);
    int d0 = l * 8;
    sn[r*256 + d0 + 0] = (v0.x - mean) * rs * lnw[d0+0] + lnb[d0+0];
    sn[r*256 + d0 + 1] = (v0.y - mean) * rs * lnw[d0+1] + lnb[d0+1];
    sn[r*256 + d0 + 2] = (v0.z - mean) * rs * lnw[d0+2] + lnb[d0+2];
    sn[r*256 + d0 + 3] = (v0.w - mean) * rs * lnw[d0+3] + lnb[d0+3];
    sn[r*256 + d0 + 4] = (v1.x - mean) * rs * lnw[d0+4] + lnb[d0+4];
    sn[r*256 + d0 + 5] = (v1.y - mean) * rs * lnw[d0+5] + lnb[d0+5];
    sn[r*256 + d0 + 6] = (v1.z - mean) * rs * lnw[d0+6] + lnb[d0+6];
    sn[r*256 + d0 + 7] = (v1.w - mean) * rs * lnw[d0+7] + lnb[d0+7];
    __syncthreads();

    float acc[8] = {0,0,0,0,0,0,0,0};
    const float4* wr  = (const float4*)(Wq + tid * 256);
    const float4* sn4 = (const float4*)sn;
    for (int d4 = 0; d4 < 64; d4++) {
        float4 w = wr[d4];
#pragma unroll
        for (int rr = 0; rr < 8; rr++) {
            float4 s = sn4[rr * 64 + d4];
            acc[rr] += w.x*s.x + w.y*s.y + w.z*s.z + w.w*s.w;
        }
    }
    const float scale = 0.0625f;
#pragma unroll
    for (int rr = 0; rr < 8; rr++)
        g_q[(b * 8 + rr) * 256 + tid] = acc[rr] * scale;
}

// =================================================================================
// K4: tensor-core attention. grid (32, 64), 256 threads, ~148 KB smem.
// Phase 1: logits = k @ q^T via mma (n = 8 slots). Phase 2: updates = attn^T @ v.
// =================================================================================
#define K4_SMEM ((128*264 + 16*132 + 256*8 + 64) * 4)

__global__ void __launch_bounds__(256, 1) k4_attn()
{
    extern __shared__ float s4[];
    float* buf = s4;                        // k: [128][260] / v: [128][264] (tf32)
    float* at  = s4 + 128 * 264;            // attn tf32 [16][132] (rows 8..15 zero)
    float* qt  = at + 16 * 132;             // q tf32 [256 dims][8 slots]
    float* wcs = qt + 256 * 8;              // colsum partials [8 warps][8 slots]
    unsigned* bufu = (unsigned*)buf;
    unsigned* atu  = (unsigned*)at;
    unsigned* qtu  = (unsigned*)qt;

    int tid = threadIdx.x;
    int w = tid >> 5, lane = tid & 31;
    int g = lane >> 2, c = lane & 3;
    int b = blockIdx.y, chunk = blockIdx.x;
    long tok0 = (long)b * 4096 + (long)chunk * 128;

    for (int i = tid; i < 2048; i += 256) {
        int s = i >> 8, d = i & 255;
        qtu[d * 8 + s] = f2tf32(g_q[b * 2048 + i]);
    }
    for (int i = tid; i < 8 * 132; i += 256) at[8 * 132 + i] = 0.f;

    {   // stage k tile (tf32, stride 260)
        const float* kb = g_k + tok0 * 256;
        for (int i = tid * 4; i < 128 * 256; i += 1024) {
            int row = i >> 8, col = i & 255;
            float4 t = *(const float4*)(kb + row * 256 + col);
            uint4 u;
            u.x = f2tf32(t.x); u.y = f2tf32(t.y);
            u.z = f2tf32(t.z); u.w = f2tf32(t.w);
            *(uint4*)(bufu + row * 260 + col) = u;
        }
    }
    __syncthreads();

    {   // phase 1: warp w -> tokens [w*16, w*16+16)
        int m0 = w * 16;
        float c0 = 0.f, c1 = 0.f, c2 = 0.f, c3 = 0.f;
#pragma unroll
        for (int ks = 0; ks < 32; ks++) {
            int k0 = ks * 8;
            unsigned a0 = bufu[(m0 + g) * 260 + k0 + c];
            unsigned a1 = bufu[(m0 + g + 8) * 260 + k0 + c];
            unsigned a2 = bufu[(m0 + g) * 260 + k0 + c + 4];
            unsigned a3 = bufu[(m0 + g + 8) * 260 + k0 + c + 4];
            unsigned b0 = qtu[(k0 + c) * 8 + g];
            unsigned b1 = qtu[(k0 + c + 4) * 8 + g];
            mma_tf32(c0, c1, c2, c3, a0, a1, a2, a3, b0, b1);
        }
        float cs0 = 0.f, cs1 = 0.f;
        {   // token m0+g: slots (2c, 2c+1) in (c0, c1)
            float m1 = fmaxf(c0, c1);
            m1 = fmaxf(m1, __shfl_xor_sync(0xffffffffu, m1, 1));
            m1 = fmaxf(m1, __shfl_xor_sync(0xffffffffu, m1, 2));
            float e0 = expf(c0 - m1), e1 = expf(c1 - m1);
            float sv = e0 + e1;
            sv += __shfl_xor_sync(0xffffffffu, sv, 1);
            sv += __shfl_xor_sync(0xffffffffu, sv, 2);
            float inv = 1.0f / sv;
            float w0 = e0 * inv + 1e-8f, w1v = e1 * inv + 1e-8f;
            atu[(2*c)   * 132 + m0 + g] = f2tf32(w0);
            atu[(2*c+1) * 132 + m0 + g] = f2tf32(w1v);
            cs0 += w0; cs1 += w1v;
        }
        {   // token m0+g+8: (c2, c3)
            float m1 = fmaxf(c2, c3);
            m1 = fmaxf(m1, __shfl_xor_sync(0xffffffffu, m1, 1));
            m1 = fmaxf(m1, __shfl_xor_sync(0xffffffffu, m1, 2));
            float e0 = expf(c2 - m1), e1 = expf(c3 - m1);
            float sv = e0 + e1;
            sv += __shfl_xor_sync(0xffffffffu, sv, 1);
            sv += __shfl_xor_sync(0xffffffffu, sv, 2);
            float inv = 1.0f / sv;
            float w0 = e0 * inv + 1e-8f, w1v = e1 * inv + 1e-8f;
            atu[(2*c)   * 132 + m0 + g + 8] = f2tf32(w0);
            atu[(2*c+1) * 132 + m0 + g + 8] = f2tf32(w1v);
            cs0 += w0; cs1 += w1v;
        }
        cs0 += __shfl_xor_sync(0xffffffffu, cs0, 4);
        cs1 += __shfl_xor_sync(0xffffffffu, cs1, 4);
        cs0 += __shfl_xor_sync(0xffffffffu, cs0, 8);
        cs1 += __shfl_xor_sync(0xffffffffu, cs1, 8);
        cs0 += __shfl_xor_sync(0xffffffffu, cs0, 16);
        cs1 += __shfl_xor_sync(0xffffffffu, cs1, 16);
        if (g == 0) { wcs[w * 8 + 2*c] = cs0; wcs[w * 8 + 2*c + 1] = cs1; }
    }
    __syncthreads();
    if (tid < 8) {
        float s = 0.f;
#pragma unroll
        for (int wi = 0; wi < 8; wi++) s += wcs[wi * 8 + tid];
        g_colp[(b * CH_ + chunk) * 8 + tid] = s;
    }

    {   // stage v tile (tf32, stride 264)
        const float* vb = g_v + tok0 * 256;
        for (int i = tid * 4; i < 128 * 256; i += 1024) {
            int row = i >> 8, col = i & 255;
            float4 t = *(const float4*)(vb + row * 256 + col);
            uint4 u;
            u.x = f2tf32(t.x); u.y = f2tf32(t.y);
            u.z = f2tf32(t.z); u.w = f2tf32(t.w);
            *(uint4*)(bufu + row * 264 + col) = u;
        }
    }
    __syncthreads();

    {   // phase 2: warp w -> dims [w*32, w*32+32)
        float acc[4][4];
#pragma unroll
        for (int nt = 0; nt < 4; nt++)
#pragma unroll
            for (int e = 0; e < 4; e++) acc[nt][e] = 0.f;
#pragma unroll
        for (int ks = 0; ks < 16; ks++) {
            int k0 = ks * 8;
            unsigned a0 = atu[g * 132 + k0 + c];
            unsigned a1 = atu[(g + 8) * 132 + k0 + c];
            unsigned a2 = atu[g * 132 + k0 + c + 4];
            unsigned a3 = atu[(g + 8) * 132 + k0 + c + 4];
#pragma unroll
            for (int nt = 0; nt < 4; nt++) {
                int n0 = w * 32 + nt * 8;
                unsigned b0 = bufu[(k0 + c) * 264 + n0 + g];
                unsigned b1 = bufu[(k0 + c + 4) * 264 + n0 + g];
                mma_tf32(acc[nt][0], acc[nt][1], acc[nt][2], acc[nt][3],
                         a0, a1, a2, a3, b0, b1);
            }
        }
        float* op = g_updp + ((long)(b * CH_ + chunk) * 8 + g) * 256;
#pragma unroll
        for (int nt = 0; nt < 4; nt++) {
            int n0 = w * 32 + nt * 8;
            *(float2*)(op + n0 + 2 * c) = make_float2(acc[nt][0], acc[nt][1]);
        }
    }
}

// =================================================================================
// K5: reduce partials over 32 chunks, divide by colsum. grid 64, 256 threads.
// =================================================================================
__global__ void __launch_bounds__(256) k5_reduce()
{
    int tid = threadIdx.x, b = blockIdx.x;
    int s = tid >> 5, g = tid & 31;
    float c = g_colp[(b * CH_ + g) * 8 + s];
#pragma unroll
    for (int off = 16; off >= 1; off >>= 1)
        c += __shfl_xor_sync(0xffffffffu, c, off);
    float4 A0 = make_float4(0,0,0,0), A1 = make_float4(0,0,0,0);
    for (int ch = 0; ch < CH_; ch++) {
        const float4* p = (const float4*)(g_updp + ((long)(b * CH_ + ch) * 8 + s) * 256 + g * 8);
        float4 u0 = p[0], u1 = p[1];
        A0.x += u0.x; A0.y += u0.y; A0.z += u0.z; A0.w += u0.w;
        A1.x += u1.x; A1.y += u1.y; A1.z += u1.z; A1.w += u1.w;
    }
    float inv = 1.0f / c;
    A0.x *= inv; A0.y *= inv; A0.z *= inv; A0.w *= inv;
    A1.x *= inv; A1.y *= inv; A1.z *= inv; A1.w *= inv;
    float4* o = (float4*)(g_upd + (b * 8 + s) * 256 + g * 8);
    o[0] = A0; o[1] = A1;
}

// =================================================================================
// K6a: GRU input/hidden gemms, grid (64, 3): batch x 256-row slice of 768.
// =================================================================================
__global__ void __launch_bounds__(256) k6a_gru_gemm(
    const float* __restrict__ w_ih, const float* __restrict__ w_hh,
    const float* __restrict__ b_ih, const float* __restrict__ b_hh)
{
    __shared__ float up[2048], hp[2048];
    int tid = threadIdx.x, b = blockIdx.x, m = blockIdx.y;
    for (int i = tid; i < 2048; i += 256) {
        up[i] = g_upd[b * 2048 + i];
        hp[i] = g_slots[b * 2048 + i];
    }
    __syncthreads();

    int o = m * 256 + tid;
    float ai[8] = {0,0,0,0,0,0,0,0};
    float ah[8] = {0,0,0,0,0,0,0,0};
    const float4* wi = (const float4*)(w_ih + o * 256);
    const float4* wh = (const float4*)(w_hh + o * 256);
    const float4* up4 = (const float4*)up;
    const float4* hp4 = (const float4*)hp;
    for (int d4 = 0; d4 < 64; d4++) {
        float4 a = wi[d4];
        float4 cH = wh[d4];
#pragma unroll
        for (int r = 0; r < 8; r++) {
            float4 u = up4[r * 64 + d4];
            float4 h = hp4[r * 64 + d4];
            ai[r] += a.x*u.x + a.y*u.y + a.z*u.z + a.w*u.w;
            ah[r] += cH.x*h.x + cH.y*h.y + cH.z*h.z + cH.w*h.w;
        }
    }
    float bi = b_ih[o], bh = b_hh[o];
#pragma unroll
    for (int r = 0; r < 8; r++) {
        g_gi[(b * 8 + r) * 768 + o] = ai[r] + bi;
        g_gh[(b * 8 + r) * 768 + o] = ah[r] + bh;
    }
}

// =================================================================================
// K6b: GRU gate combine + LayerNorm.  grid 64, 256 threads.
// =================================================================================
__global__ void __launch_bounds__(256) k6b_gate_ln(
    const float* __restrict__ lnw, const float* __restrict__ lnb)
{
    __shared__ float ns[2048];
    int tid = threadIdx.x, b = blockIdx.x;
    int d = tid;
#pragma unroll
    for (int r = 0; r < 8; r++) {
        long base = (long)(b * 8 + r) * 768;
        float ir = g_gi[base + d],       hr = g_gh[base + d];
        float iz = g_gi[base + 256 + d], hz = g_gh[base + 256 + d];
        float in_ = g_gi[base + 512 + d], hn = g_gh[base + 512 + d];
        float rg = 1.0f / (1.0f + expf(-(ir + hr)));
        float zg = 1.0f / (1.0f + expf(-(iz + hz)));
        float ng = tanhf(in_ + rg * hn);
        float h = g_slots[(b * 8 + r) * 256 + d];
        float nsv = (1.0f - zg) * ng + zg * h;
        ns[r * 256 + d] = nsv;
        g_ns[(b * 8 + r) * 256 + d] = nsv;
    }
    __syncthreads();

    int r = tid >> 5, l = tid & 31;
    const float4* nr = (const float4*)(ns + r * 256);
    float4 v0 = nr[l * 2], v1 = nr[l * 2 + 1];
    float s1 = v0.x + v0.y + v0.z + v0.w + v1.x + v1.y + v1.z + v1.w;
    float s2 = v0.x*v0.x + v0.y*v0.y + v0.z*v0.z + v0.w*v0.w
             + v1.x*v1.x + v1.y*v1.y + v1.z*v1.z + v1.w*v1.w;
#pragma unroll
    for (int off = 16; off >= 1; off >>= 1) {
        s1 += __shfl_xor_sync(0xffffffffu, s1, off);
        s2 += __shfl_xor_sync(0xffffffffu, s2, off);
    }
    float mean = s1 * (1.0f / 256.0f);
    float var  = s2 * (1.0f / 256.0f) - mean * mean;
    float rs   = rsqrtf(var + 1e-5f);
    int d0 = l * 8;
    float* sp = g_sn + (b * 8 + r) * 256;
    sp[d0 + 0] = (v0.x - mean) * rs * lnw[d0+0] + lnb[d0+0];
    sp[d0 + 1] = (v0.y - mean) * rs * lnw[d0+1] + lnb[d0+1];
    sp[d0 + 2] = (v0.z - mean) * rs * lnw[d0+2] + lnb[d0+2];
    sp[d0 + 3] = (v0.w - mean) * rs * lnw[d0+3] + lnb[d0+3];
    sp[d0 + 4] = (v1.x - mean) * rs * lnw[d0+4] + lnb[d0+4];
    sp[d0 + 5] = (v1.y - mean) * rs * lnw[d0+5] + lnb[d0+5];
    sp[d0 + 6] = (v1.z - mean) * rs * lnw[d0+6] + lnb[d0+6];
    sp[d0 + 7] = (v1.w - mean) * rs * lnw[d0+7] + lnb[d0+7];
}

// =================================================================================
// K6c: h1 = relu(sn @ w1^T + b1).  grid (64, 2): batch x 256-row slice of 512.
// =================================================================================
__global__ void __launch_bounds__(256) k6c_mlp1(
    const float* __restrict__ w1, const float* __restrict__ b1)
{
    __shared__ float sn[2048];
    int tid = threadIdx.x, b = blockIdx.x, m = blockIdx.y;
    for (int i = tid; i < 2048; i += 256) sn[i] = g_sn[b * 2048 + i];
    __syncthreads();

    int o = m * 256 + tid;
    float a[8] = {0,0,0,0,0,0,0,0};
    const float4* wr = (const float4*)(w1 + o * 256);
    const float4* sn4 = (const float4*)sn;
    for (int d4 = 0; d4 < 64; d4++) {
        float4 wv = wr[d4];
#pragma unroll
        for (int r = 0; r < 8; r++) {
            float4 s = sn4[r * 64 + d4];
            a[r] += wv.x*s.x + wv.y*s.y + wv.z*s.z + wv.w*s.w;
        }
    }
    float bb = b1[o];
#pragma unroll
    for (int r = 0; r < 8; r++)
        g_h1[(b * 8 + r) * 512 + o] = fmaxf(a[r] + bb, 0.0f);
}

// =================================================================================
// K6d: out = ns + h1 @ w2^T + b2.  grid (64, 2): batch x 128-dim slice, 128 thr.
// =================================================================================
__global__ void __launch_bounds__(128) k6d_mlp2(
    const float* __restrict__ w2, const float* __restrict__ b2, float* out2)
{
    __shared__ float h1[4096];
    int tid = threadIdx.x, b = blockIdx.x, half = blockIdx.y;
    for (int i = tid * 4; i < 4096; i += 512)
        *(float4*)(h1 + i) = *(const float4*)(g_h1 + b * 4096 + i);
    __syncthreads();

    int o = half * 128 + tid;
    float a[8] = {0,0,0,0,0,0,0,0};
    const float4* wr = (const float4*)(w2 + o * 512);
    const float4* h14 = (const float4*)h1;
    for (int d4 = 0; d4 < 128; d4++) {
        float4 wv = wr[d4];
#pragma unroll
        for (int r = 0; r < 8; r++) {
            float4 h = h14[r * 128 + d4];
            a[r] += wv.x*h.x + wv.y*h.y + wv.z*h.z + wv.w*h.w;
        }
    }
    float bb = b2[o];
#pragma unroll
    for (int r = 0; r < 8; r++) {
        float vout = g_ns[(b * 8 + r) * 256 + o] + a[r] + bb;
        g_slots[(b * 8 + r) * 256 + o] = vout;
        if (out2) out2[(b * 8 + r) * 256 + o] = vout;
    }
}

// =================================================================================
extern "C" void kernel_launch(void* const* d_in, const int* in_sizes, int n_in,
                              void* d_out, int out_size) {
    const float* inputs  = (const float*)d_in[0];
    const float* noise   = (const float*)d_in[1];
    const float* ln_in_w = (const float*)d_in[2];
    const float* ln_in_b = (const float*)d_in[3];
    const float* ln_sl_w = (const float*)d_in[4];
    const float* ln_sl_b = (const float*)d_in[5];
    const float* ln_ml_w = (const float*)d_in[6];
    const float* ln_ml_b = (const float*)d_in[7];
    const float* mu      = (const float*)d_in[8];
    const float* ls      = (const float*)d_in[9];
    const float* Wq      = (const float*)d_in[10];
    const float* Wk      = (const float*)d_in[11];
    const float* Wv      = (const float*)d_in[12];
    const float* w_ih    = (const float*)d_in[13];
    const float* w_hh    = (const float*)d_in[14];
    const float* b_ih    = (const float*)d_in[15];
    const float* b_hh    = (const float*)d_in[16];
    const float* w1      = (const float*)d_in[17];
    const float* b1      = (const float*)d_in[18];
    const float* w2      = (const float*)d_in[19];
    const float* b2      = (const float*)d_in[20];
    float* out = (float*)d_out;

    cudaFuncSetAttribute(k1_proj, cudaFuncAttributeMaxDynamicSharedMemorySize, K1_SMEM);
    cudaFuncSetAttribute(k4_attn, cudaFuncAttributeMaxDynamicSharedMemorySize, K4_SMEM);

    k0_init<<<512, 256>>>(noise, mu, ls);
    k1_proj<<<dim3(2048, 2), 256, K1_SMEM>>>(inputs, Wk, Wv, ln_in_w, ln_in_b);
    for (int it = 0; it < 3; it++) {
        k3_q<<<64, 256>>>(Wq, ln_sl_w, ln_sl_b);
        k4_attn<<<dim3(CH_, 64), 256, K4_SMEM>>>();
        k5_reduce<<<64, 256>>>();
        k6a_gru_gemm<<<dim3(64, 3), 256>>>(w_ih, w_hh, b_ih, b_hh);
        k6b_gate_ln<<<64, 256>>>(ln_ml_w, ln_ml_b);
        k6c_mlp1<<<dim3(64, 2), 256>>>(w1, b1);
        k6d_mlp2<<<dim3(64, 2), 128>>>(w2, b2, (it == 2) ? out : nullptr);
    }
}

// round 5
// speedup vs baseline: 2.0934x; 1.2006x over previous
#include <cuda_runtime.h>

#define B_ 64
#define N_ 4096
#define D_ 256
#define S_ 8
#define H_ 512
#define CH_ 32

// ---------------- scratch (device globals; no allocation allowed) ----------------
__device__ float g_k[B_*N_*D_];
__device__ float g_v[B_*N_*D_];
__device__ float g_slots[B_*S_*D_];
__device__ float g_q[B_*S_*D_];
__device__ float g_updp[B_*CH_*S_*D_];
__device__ float g_colp[B_*CH_*S_];
__device__ float g_gi[B_*S_*768];
__device__ float g_gh[B_*S_*768];
__device__ float g_ns[B_*S_*D_];
__device__ float g_sn[B_*S_*D_];
__device__ float g_h1[B_*S_*H_];

// ---------------- helpers --------------------------------------------------------
// NOTE: tf32 mma consumes fp32 bit patterns (HW uses the top 19 bits), so we feed
// raw float bits everywhere instead of cvt.rna.tf32 — removes all CVT traffic.
__device__ __forceinline__ void mma_tf32(float& c0, float& c1, float& c2, float& c3,
                                         unsigned a0, unsigned a1, unsigned a2, unsigned a3,
                                         unsigned b0, unsigned b1) {
    asm volatile(
        "mma.sync.aligned.m16n8k8.row.col.f32.tf32.tf32.f32 "
        "{%0,%1,%2,%3}, {%4,%5,%6,%7}, {%8,%9}, {%0,%1,%2,%3};"
        : "+f"(c0), "+f"(c1), "+f"(c2), "+f"(c3)
        : "r"(a0), "r"(a1), "r"(a2), "r"(a3), "r"(b0), "r"(b1));
}

// =================================================================================
// K0: slots = mu + exp(log_sigma) * noise
// =================================================================================
__global__ void k0_init(const float* __restrict__ noise,
                        const float* __restrict__ mu,
                        const float* __restrict__ ls) {
    int i = blockIdx.x * 256 + threadIdx.x;
    int d = i & 255;
    g_slots[i] = mu[d] + expf(ls[d]) * noise[i];
}

// =================================================================================
// K1: fused LayerNorm + k/v projection via tf32 mma (raw-bit operands).
// grid (2048, 2). smem: xs[128][260] fp32 + ws[256][36] (W k-chunk, untransposed).
// =================================================================================
#define XS_STR 260
#define WS_STR 36
#define K1_SMEM ((128*XS_STR + 256*WS_STR) * 4)

__global__ void __launch_bounds__(256, 1) k1_proj(
    const float* __restrict__ inp, const float* __restrict__ Wk,
    const float* __restrict__ Wv, const float* __restrict__ lnw,
    const float* __restrict__ lnb)
{
    extern __shared__ float sm[];
    float* xs = sm;                       // [128][260]
    float* ws = sm + 128 * XS_STR;        // [256][36]
    unsigned* xs_u = (unsigned*)xs;
    unsigned* ws_u = (unsigned*)ws;

    int tid = threadIdx.x;
    const float* W = (blockIdx.y == 0) ? Wk : Wv;
    float* outp = (blockIdx.y == 0) ? g_k : g_v;
    long tok0 = (long)blockIdx.x * 128;

    {   // LN: 2 threads per token
        int tok = tid >> 1, half = tid & 1;
        const float4* xr = (const float4*)(inp + (tok0 + tok) * 256 + half * 128);
        float* xw = xs + tok * XS_STR + half * 128;
        float s1 = 0.f, s2 = 0.f;
#pragma unroll
        for (int j = 0; j < 32; j++) {
            float4 t = xr[j];
            s1 += t.x + t.y + t.z + t.w;
            s2 += t.x*t.x + t.y*t.y + t.z*t.z + t.w*t.w;
            *(float4*)(xw + j * 4) = t;
        }
        s1 += __shfl_xor_sync(0xffffffffu, s1, 1);
        s2 += __shfl_xor_sync(0xffffffffu, s2, 1);
        float mean = s1 * (1.0f / 256.0f);
        float var  = s2 * (1.0f / 256.0f) - mean * mean;
        float rs   = rsqrtf(var + 1e-5f);
        const float4* lw4 = (const float4*)(lnw + half * 128);
        const float4* lb4 = (const float4*)(lnb + half * 128);
#pragma unroll
        for (int j = 0; j < 32; j++) {
            float4 t = *(float4*)(xw + j * 4);
            float4 w4 = __ldg(lw4 + j);
            float4 b4 = __ldg(lb4 + j);
            t.x = (t.x - mean) * rs * w4.x + b4.x;
            t.y = (t.y - mean) * rs * w4.y + b4.y;
            t.z = (t.z - mean) * rs * w4.z + b4.z;
            t.w = (t.w - mean) * rs * w4.w + b4.w;
            *(float4*)(xw + j * 4) = t;
        }
    }

    int w = tid >> 5, lane = tid & 31;
    int m0 = (w >> 2) * 64, n0 = (w & 3) * 64;
    int g = lane >> 2, c = lane & 3;

    float acc[4][8][4];
#pragma unroll
    for (int mt = 0; mt < 4; mt++)
#pragma unroll
        for (int nt = 0; nt < 8; nt++)
#pragma unroll
            for (int e = 0; e < 4; e++) acc[mt][nt][e] = 0.f;

    for (int kc = 0; kc < 256; kc += 32) {
        __syncthreads();
        {   // stage W[tid][kc..kc+31] untransposed (float4 copy, no cvt)
            const float4* wr = (const float4*)(W + tid * 256 + kc);
            float4* wsr = (float4*)(ws + tid * WS_STR);
#pragma unroll
            for (int j = 0; j < 8; j++) wsr[j] = wr[j];
        }
        __syncthreads();
#pragma unroll
        for (int ks = 0; ks < 4; ks++) {
            int k0 = ks * 8;
            unsigned a[4][4];
#pragma unroll
            for (int mt = 0; mt < 4; mt++) {
                int rb = (m0 + mt * 16 + g) * XS_STR + kc + k0 + c;
                a[mt][0] = xs_u[rb];
                a[mt][1] = xs_u[rb + 8 * XS_STR];
                a[mt][2] = xs_u[rb + 4];
                a[mt][3] = xs_u[rb + 8 * XS_STR + 4];
            }
            unsigned b[8][2];
#pragma unroll
            for (int nt = 0; nt < 8; nt++) {
                int nr = (n0 + nt * 8 + g) * WS_STR + k0 + c;
                b[nt][0] = ws_u[nr];
                b[nt][1] = ws_u[nr + 4];
            }
#pragma unroll
            for (int mt = 0; mt < 4; mt++)
#pragma unroll
                for (int nt = 0; nt < 8; nt++)
                    mma_tf32(acc[mt][nt][0], acc[mt][nt][1],
                             acc[mt][nt][2], acc[mt][nt][3],
                             a[mt][0], a[mt][1], a[mt][2], a[mt][3],
                             b[nt][0], b[nt][1]);
        }
    }
#pragma unroll
    for (int mt = 0; mt < 4; mt++) {
        long r0 = tok0 + m0 + mt * 16 + g;
#pragma unroll
        for (int nt = 0; nt < 8; nt++) {
            int col = n0 + nt * 8 + c * 2;
            *(float2*)(outp + r0 * 256 + col) = make_float2(acc[mt][nt][0], acc[mt][nt][1]);
            *(float2*)(outp + (r0 + 8) * 256 + col) = make_float2(acc[mt][nt][2], acc[mt][nt][3]);
        }
    }
}

// =================================================================================
// K3: q = LN(slots) @ Wq^T * scale.  grid 64, 256 threads.
// =================================================================================
__global__ void __launch_bounds__(256) k3_q(
    const float* __restrict__ Wq, const float* __restrict__ lnw,
    const float* __restrict__ lnb)
{
    __shared__ float sn[8 * 256];
    int tid = threadIdx.x, b = blockIdx.x;
    int r = tid >> 5, l = tid & 31;

    const float4* sr = (const float4*)(g_slots + (b * 8 + r) * 256);
    float4 v0 = sr[l * 2], v1 = sr[l * 2 + 1];
    float s1 = v0.x + v0.y + v0.z + v0.w + v1.x + v1.y + v1.z + v1.w;
    float s2 = v0.x*v0.x + v0.y*v0.y + v0.z*v0.z + v0.w*v0.w
             + v1.x*v1.x + v1.y*v1.y + v1.z*v1.z + v1.w*v1.w;
#pragma unroll
    for (int off = 16; off >= 1; off >>= 1) {
        s1 += __shfl_xor_sync(0xffffffffu, s1, off);
        s2 += __shfl_xor_sync(0xffffffffu, s2, off);
    }
    float mean = s1 * (1.0f / 256.0f);
    float var  = s2 * (1.0f / 256.0f) - mean * mean;
    float rs   = rsqrtf(var + 1e-5f);
    int d0 = l * 8;
    sn[r*256 + d0 + 0] = (v0.x - mean) * rs * lnw[d0+0] + lnb[d0+0];
    sn[r*256 + d0 + 1] = (v0.y - mean) * rs * lnw[d0+1] + lnb[d0+1];
    sn[r*256 + d0 + 2] = (v0.z - mean) * rs * lnw[d0+2] + lnb[d0+2];
    sn[r*256 + d0 + 3] = (v0.w - mean) * rs * lnw[d0+3] + lnb[d0+3];
    sn[r*256 + d0 + 4] = (v1.x - mean) * rs * lnw[d0+4] + lnb[d0+4];
    sn[r*256 + d0 + 5] = (v1.y - mean) * rs * lnw[d0+5] + lnb[d0+5];
    sn[r*256 + d0 + 6] = (v1.z - mean) * rs * lnw[d0+6] + lnb[d0+6];
    sn[r*256 + d0 + 7] = (v1.w - mean) * rs * lnw[d0+7] + lnb[d0+7];
    __syncthreads();

    float acc[8] = {0,0,0,0,0,0,0,0};
    const float4* wr  = (const float4*)(Wq + tid * 256);
    const float4* sn4 = (const float4*)sn;
    for (int d4 = 0; d4 < 64; d4++) {
        float4 w = wr[d4];
#pragma unroll
        for (int rr = 0; rr < 8; rr++) {
            float4 s = sn4[rr * 64 + d4];
            acc[rr] += w.x*s.x + w.y*s.y + w.z*s.z + w.w*s.w;
        }
    }
    const float scale = 0.0625f;
#pragma unroll
    for (int rr = 0; rr < 8; rr++)
        g_q[(b * 8 + rr) * 256 + tid] = acc[rr] * scale;
}

// =================================================================================
// K4: smem-free tensor-core attention. grid (32, 64), 256 threads, 17 KB smem.
// Phase 1: logits = k @ q^T (k direct from gmem). Phase 2: updates = attn^T @ v
// (v direct from gmem). All tf32 operands are raw fp32 bits.
// =================================================================================
__global__ void __launch_bounds__(256, 3) k4_attn()
{
    __shared__ float at[16 * 132];      // attn weights [slot-row 16][token 132]
    __shared__ unsigned qt[256 * 8];    // q bits [dim][slot]
    __shared__ float wcs[8][8];
    unsigned* atu = (unsigned*)at;

    int tid = threadIdx.x;
    int w = tid >> 5, lane = tid & 31;
    int g = lane >> 2, c = lane & 3;
    int b = blockIdx.y, chunk = blockIdx.x;
    long tok0 = (long)b * 4096 + (long)chunk * 128;

    for (int i = tid; i < 2048; i += 256) {
        int s = i >> 8, d = i & 255;
        qt[d * 8 + s] = __float_as_uint(g_q[b * 2048 + i]);
    }
    for (int i = tid; i < 8 * 132; i += 256) at[8 * 132 + i] = 0.f;
    __syncthreads();

    {   // phase 1: warp w -> tokens [w*16, w*16+16)
        int m0 = w * 16;
        const unsigned* kb = (const unsigned*)(g_k + tok0 * 256);
        int rA = (m0 + g) * 256, rB = (m0 + g + 8) * 256;
        float c0 = 0.f, c1 = 0.f, c2 = 0.f, c3 = 0.f;
#pragma unroll 8
        for (int ks = 0; ks < 32; ks++) {
            int k0 = ks * 8;
            unsigned a0 = kb[rA + k0 + c];
            unsigned a1 = kb[rB + k0 + c];
            unsigned a2 = kb[rA + k0 + c + 4];
            unsigned a3 = kb[rB + k0 + c + 4];
            unsigned b0 = qt[(k0 + c) * 8 + g];
            unsigned b1 = qt[(k0 + c + 4) * 8 + g];
            mma_tf32(c0, c1, c2, c3, a0, a1, a2, a3, b0, b1);
        }
        float cs0 = 0.f, cs1 = 0.f;
        {   // token m0+g: slots (2c, 2c+1)
            float m1 = fmaxf(c0, c1);
            m1 = fmaxf(m1, __shfl_xor_sync(0xffffffffu, m1, 1));
            m1 = fmaxf(m1, __shfl_xor_sync(0xffffffffu, m1, 2));
            float e0 = expf(c0 - m1), e1 = expf(c1 - m1);
            float sv = e0 + e1;
            sv += __shfl_xor_sync(0xffffffffu, sv, 1);
            sv += __shfl_xor_sync(0xffffffffu, sv, 2);
            float inv = 1.0f / sv;
            float w0 = e0 * inv + 1e-8f, w1v = e1 * inv + 1e-8f;
            at[(2*c)   * 132 + m0 + g] = w0;
            at[(2*c+1) * 132 + m0 + g] = w1v;
            cs0 += w0; cs1 += w1v;
        }
        {   // token m0+g+8
            float m1 = fmaxf(c2, c3);
            m1 = fmaxf(m1, __shfl_xor_sync(0xffffffffu, m1, 1));
            m1 = fmaxf(m1, __shfl_xor_sync(0xffffffffu, m1, 2));
            float e0 = expf(c2 - m1), e1 = expf(c3 - m1);
            float sv = e0 + e1;
            sv += __shfl_xor_sync(0xffffffffu, sv, 1);
            sv += __shfl_xor_sync(0xffffffffu, sv, 2);
            float inv = 1.0f / sv;
            float w0 = e0 * inv + 1e-8f, w1v = e1 * inv + 1e-8f;
            at[(2*c)   * 132 + m0 + g + 8] = w0;
            at[(2*c+1) * 132 + m0 + g + 8] = w1v;
            cs0 += w0; cs1 += w1v;
        }
        cs0 += __shfl_xor_sync(0xffffffffu, cs0, 4);
        cs1 += __shfl_xor_sync(0xffffffffu, cs1, 4);
        cs0 += __shfl_xor_sync(0xffffffffu, cs0, 8);
        cs1 += __shfl_xor_sync(0xffffffffu, cs1, 8);
        cs0 += __shfl_xor_sync(0xffffffffu, cs0, 16);
        cs1 += __shfl_xor_sync(0xffffffffu, cs1, 16);
        if (g == 0) { wcs[w][2*c] = cs0; wcs[w][2*c + 1] = cs1; }
    }
    __syncthreads();
    if (tid < 8) {
        float s = 0.f;
#pragma unroll
        for (int wi = 0; wi < 8; wi++) s += wcs[wi][tid];
        g_colp[(b * CH_ + chunk) * 8 + tid] = s;
    }

    {   // phase 2: warp w -> dims [w*32, w*32+32); v direct from gmem
        const unsigned* vb = (const unsigned*)(g_v + tok0 * 256);
        float acc[4][4];
#pragma unroll
        for (int nt = 0; nt < 4; nt++)
#pragma unroll
            for (int e = 0; e < 4; e++) acc[nt][e] = 0.f;
#pragma unroll 2
        for (int ks = 0; ks < 16; ks++) {
            int k0 = ks * 8;
            unsigned a0 = atu[g * 132 + k0 + c];
            unsigned a1 = atu[(g + 8) * 132 + k0 + c];
            unsigned a2 = atu[g * 132 + k0 + c + 4];
            unsigned a3 = atu[(g + 8) * 132 + k0 + c + 4];
            int rc = (k0 + c) * 256, rc4 = (k0 + c + 4) * 256;
#pragma unroll
            for (int nt = 0; nt < 4; nt++) {
                int n0 = w * 32 + nt * 8 + g;
                unsigned b0 = vb[rc + n0];
                unsigned b1 = vb[rc4 + n0];
                mma_tf32(acc[nt][0], acc[nt][1], acc[nt][2], acc[nt][3],
                         a0, a1, a2, a3, b0, b1);
            }
        }
        float* op = g_updp + ((long)(b * CH_ + chunk) * 8 + g) * 256;
#pragma unroll
        for (int nt = 0; nt < 4; nt++) {
            int n0 = w * 32 + nt * 8;
            *(float2*)(op + n0 + 2 * c) = make_float2(acc[nt][0], acc[nt][1]);
        }
    }
}

// =================================================================================
// K6a: chunk-reduce + colsum-normalize (folded k5) + GRU gemms.  grid (64, 3).
// =================================================================================
__global__ void __launch_bounds__(256) k6a_gru_gemm(
    const float* __restrict__ w_ih, const float* __restrict__ w_hh,
    const float* __restrict__ b_ih, const float* __restrict__ b_hh)
{
    __shared__ float up[2048], hp[2048], cs[8];
    int tid = threadIdx.x, b = blockIdx.x, m = blockIdx.y;

    {   // colsum per slot (warp s reduces its 32 chunk partials)
        int s = tid >> 5, l = tid & 31;
        float c = g_colp[(b * CH_ + l) * 8 + s];
#pragma unroll
        for (int off = 16; off >= 1; off >>= 1)
            c += __shfl_xor_sync(0xffffffffu, c, off);
        if (l == 0) cs[s] = c;
    }
    __syncthreads();

    for (int i = tid; i < 2048; i += 256) {
        const float* p = g_updp + (long)b * CH_ * 2048 + i;
        float a = 0.f;
#pragma unroll 8
        for (int ch = 0; ch < CH_; ch++) a += p[ch * 2048];
        up[i] = a / cs[i >> 8];
        hp[i] = g_slots[b * 2048 + i];
    }
    __syncthreads();

    int o = m * 256 + tid;
    float ai[8] = {0,0,0,0,0,0,0,0};
    float ah[8] = {0,0,0,0,0,0,0,0};
    const float4* wi = (const float4*)(w_ih + o * 256);
    const float4* wh = (const float4*)(w_hh + o * 256);
    const float4* up4 = (const float4*)up;
    const float4* hp4 = (const float4*)hp;
    for (int d4 = 0; d4 < 64; d4++) {
        float4 a = wi[d4];
        float4 cH = wh[d4];
#pragma unroll
        for (int r = 0; r < 8; r++) {
            float4 u = up4[r * 64 + d4];
            float4 h = hp4[r * 64 + d4];
            ai[r] += a.x*u.x + a.y*u.y + a.z*u.z + a.w*u.w;
            ah[r] += cH.x*h.x + cH.y*h.y + cH.z*h.z + cH.w*h.w;
        }
    }
    float bi = b_ih[o], bh = b_hh[o];
#pragma unroll
    for (int r = 0; r < 8; r++) {
        g_gi[(b * 8 + r) * 768 + o] = ai[r] + bi;
        g_gh[(b * 8 + r) * 768 + o] = ah[r] + bh;
    }
}

// =================================================================================
// K6b: GRU gate combine + LayerNorm.  grid 64, 256 threads.
// =================================================================================
__global__ void __launch_bounds__(256) k6b_gate_ln(
    const float* __restrict__ lnw, const float* __restrict__ lnb)
{
    __shared__ float ns[2048];
    int tid = threadIdx.x, b = blockIdx.x;
    int d = tid;
#pragma unroll
    for (int r = 0; r < 8; r++) {
        long base = (long)(b * 8 + r) * 768;
        float ir = g_gi[base + d],       hr = g_gh[base + d];
        float iz = g_gi[base + 256 + d], hz = g_gh[base + 256 + d];
        float in_ = g_gi[base + 512 + d], hn = g_gh[base + 512 + d];
        float rg = 1.0f / (1.0f + expf(-(ir + hr)));
        float zg = 1.0f / (1.0f + expf(-(iz + hz)));
        float ng = tanhf(in_ + rg * hn);
        float h = g_slots[(b * 8 + r) * 256 + d];
        float nsv = (1.0f - zg) * ng + zg * h;
        ns[r * 256 + d] = nsv;
        g_ns[(b * 8 + r) * 256 + d] = nsv;
    }
    __syncthreads();

    int r = tid >> 5, l = tid & 31;
    const float4* nr = (const float4*)(ns + r * 256);
    float4 v0 = nr[l * 2], v1 = nr[l * 2 + 1];
    float s1 = v0.x + v0.y + v0.z + v0.w + v1.x + v1.y + v1.z + v1.w;
    float s2 = v0.x*v0.x + v0.y*v0.y + v0.z*v0.z + v0.w*v0.w
             + v1.x*v1.x + v1.y*v1.y + v1.z*v1.z + v1.w*v1.w;
#pragma unroll
    for (int off = 16; off >= 1; off >>= 1) {
        s1 += __shfl_xor_sync(0xffffffffu, s1, off);
        s2 += __shfl_xor_sync(0xffffffffu, s2, off);
    }
    float mean = s1 * (1.0f / 256.0f);
    float var  = s2 * (1.0f / 256.0f) - mean * mean;
    float rs   = rsqrtf(var + 1e-5f);
    int d0 = l * 8;
    float* sp = g_sn + (b * 8 + r) * 256;
    sp[d0 + 0] = (v0.x - mean) * rs * lnw[d0+0] + lnb[d0+0];
    sp[d0 + 1] = (v0.y - mean) * rs * lnw[d0+1] + lnb[d0+1];
    sp[d0 + 2] = (v0.z - mean) * rs * lnw[d0+2] + lnb[d0+2];
    sp[d0 + 3] = (v0.w - mean) * rs * lnw[d0+3] + lnb[d0+3];
    sp[d0 + 4] = (v1.x - mean) * rs * lnw[d0+4] + lnb[d0+4];
    sp[d0 + 5] = (v1.y - mean) * rs * lnw[d0+5] + lnb[d0+5];
    sp[d0 + 6] = (v1.z - mean) * rs * lnw[d0+6] + lnb[d0+6];
    sp[d0 + 7] = (v1.w - mean) * rs * lnw[d0+7] + lnb[d0+7];
}

// =================================================================================
// K6c: h1 = relu(sn @ w1^T + b1).  grid (64, 2).
// =================================================================================
__global__ void __launch_bounds__(256) k6c_mlp1(
    const float* __restrict__ w1, const float* __restrict__ b1)
{
    __shared__ float sn[2048];
    int tid = threadIdx.x, b = blockIdx.x, m = blockIdx.y;
    for (int i = tid; i < 2048; i += 256) sn[i] = g_sn[b * 2048 + i];
    __syncthreads();

    int o = m * 256 + tid;
    float a[8] = {0,0,0,0,0,0,0,0};
    const float4* wr = (const float4*)(w1 + o * 256);
    const float4* sn4 = (const float4*)sn;
    for (int d4 = 0; d4 < 64; d4++) {
        float4 wv = wr[d4];
#pragma unroll
        for (int r = 0; r < 8; r++) {
            float4 s = sn4[r * 64 + d4];
            a[r] += wv.x*s.x + wv.y*s.y + wv.z*s.z + wv.w*s.w;
        }
    }
    float bb = b1[o];
#pragma unroll
    for (int r = 0; r < 8; r++)
        g_h1[(b * 8 + r) * 512 + o] = fmaxf(a[r] + bb, 0.0f);
}

// =================================================================================
// K6d: out = ns + h1 @ w2^T + b2.  grid (64, 2), 128 threads.
// =================================================================================
__global__ void __launch_bounds__(128) k6d_mlp2(
    const float* __restrict__ w2, const float* __restrict__ b2, float* out2)
{
    __shared__ float h1[4096];
    int tid = threadIdx.x, b = blockIdx.x, half = blockIdx.y;
    for (int i = tid * 4; i < 4096; i += 512)
        *(float4*)(h1 + i) = *(const float4*)(g_h1 + b * 4096 + i);
    __syncthreads();

    int o = half * 128 + tid;
    float a[8] = {0,0,0,0,0,0,0,0};
    const float4* wr = (const float4*)(w2 + o * 512);
    const float4* h14 = (const float4*)h1;
    for (int d4 = 0; d4 < 128; d4++) {
        float4 wv = wr[d4];
#pragma unroll
        for (int r = 0; r < 8; r++) {
            float4 h = h14[r * 128 + d4];
            a[r] += wv.x*h.x + wv.y*h.y + wv.z*h.z + wv.w*h.w;
        }
    }
    float bb = b2[o];
#pragma unroll
    for (int r = 0; r < 8; r++) {
        float vout = g_ns[(b * 8 + r) * 256 + o] + a[r] + bb;
        g_slots[(b * 8 + r) * 256 + o] = vout;
        if (out2) out2[(b * 8 + r) * 256 + o] = vout;
    }
}

// =================================================================================
extern "C" void kernel_launch(void* const* d_in, const int* in_sizes, int n_in,
                              void* d_out, int out_size) {
    const float* inputs  = (const float*)d_in[0];
    const float* noise   = (const float*)d_in[1];
    const float* ln_in_w = (const float*)d_in[2];
    const float* ln_in_b = (const float*)d_in[3];
    const float* ln_sl_w = (const float*)d_in[4];
    const float* ln_sl_b = (const float*)d_in[5];
    const float* ln_ml_w = (const float*)d_in[6];
    const float* ln_ml_b = (const float*)d_in[7];
    const float* mu      = (const float*)d_in[8];
    const float* ls      = (const float*)d_in[9];
    const float* Wq      = (const float*)d_in[10];
    const float* Wk      = (const float*)d_in[11];
    const float* Wv      = (const float*)d_in[12];
    const float* w_ih    = (const float*)d_in[13];
    const float* w_hh    = (const float*)d_in[14];
    const float* b_ih    = (const float*)d_in[15];
    const float* b_hh    = (const float*)d_in[16];
    const float* w1      = (const float*)d_in[17];
    const float* b1      = (const float*)d_in[18];
    const float* w2      = (const float*)d_in[19];
    const float* b2      = (const float*)d_in[20];
    float* out = (float*)d_out;

    cudaFuncSetAttribute(k1_proj, cudaFuncAttributeMaxDynamicSharedMemorySize, K1_SMEM);

    k0_init<<<512, 256>>>(noise, mu, ls);
    k1_proj<<<dim3(2048, 2), 256, K1_SMEM>>>(inputs, Wk, Wv, ln_in_w, ln_in_b);
    for (int it = 0; it < 3; it++) {
        k3_q<<<64, 256>>>(Wq, ln_sl_w, ln_sl_b);
        k4_attn<<<dim3(CH_, 64), 256>>>();
        k6a_gru_gemm<<<dim3(64, 3), 256>>>(w_ih, w_hh, b_ih, b_hh);
        k6b_gate_ln<<<64, 256>>>(ln_ml_w, ln_ml_b);
        k6c_mlp1<<<dim3(64, 2), 256>>>(w1, b1);
        k6d_mlp2<<<dim3(64, 2), 128>>>(w2, b2, (it == 2) ? out : nullptr);
    }
}